// round 5
// baseline (speedup 1.0000x reference)
#include <cuda_runtime.h>
#include <math.h>
#include <stdint.h>

#define Nn 51200
#define Ee 819200
#define Bb 64

typedef unsigned long long ull;

// ---------------- scratch (__device__ globals; allocation-free) ----------------
struct __align__(32) EdgeRec { float4 basis; int src; int widx; int p0; int p1; };

__device__ int     d_cnt[Nn];
__device__ int     d_cur[Nn];
__device__ int     d_off[Nn + 1];
__device__ EdgeRec d_edge[Ee];
__device__ float   d_W1p[192 * 32];          // rows 0..174 = W1 flat, 175..181 = root1, rest 0
__device__ float   d_W2p[832 * 64];          // rows 0..799 = W2 flat, 800..831 = root2
__device__ float   d_U1[(size_t)Nn * 192];
__device__ float   d_h1[(size_t)Nn * 32];
__device__ float   d_h2[(size_t)Nn * 64];

__device__ __forceinline__ float eluf(float v) { return v > 0.f ? v : (expf(v) - 1.f); }

__device__ __forceinline__ void ffma2(ull& d, ull a, ull b) {
    asm("fma.rn.f32x2 %0, %1, %2, %0;" : "+l"(d) : "l"(a), "l"(b));
}
__device__ __forceinline__ ull pack2(float x, float y) {
    ull r;
    asm("mov.b64 %0, {%1, %2};" : "=l"(r) : "f"(x), "f"(y));
    return r;
}
__device__ __forceinline__ float2 unpk(ull v) {
    float2 r;
    asm("mov.b64 {%0,%1}, %2;" : "=f"(r.x), "=f"(r.y) : "l"(v));
    return r;
}

// ---------------- CSR build ----------------
__global__ void k_zero() {
    int i = blockIdx.x * blockDim.x + threadIdx.x;
    if (i < Nn) { d_cnt[i] = 0; d_cur[i] = 0; }
}

__global__ void k_hist(const int* __restrict__ dst) {
    int e = blockIdx.x * blockDim.x + threadIdx.x;
    if (e < Ee) atomicAdd(&d_cnt[dst[e]], 1);
}

__global__ void k_scan() {
    __shared__ int s[1024];
    int t = threadIdx.x;
    const int CH = (Nn + 1023) / 1024;  // 50
    int base = t * CH;
    int sum = 0;
    for (int j = 0; j < CH; j++) {
        int idx = base + j;
        if (idx < Nn) sum += d_cnt[idx];
    }
    s[t] = sum;
    __syncthreads();
    for (int ofs = 1; ofs < 1024; ofs <<= 1) {
        int v = (t >= ofs) ? s[t - ofs] : 0;
        __syncthreads();
        if (t >= ofs) s[t] += v;
        __syncthreads();
    }
    int run = (t == 0) ? 0 : s[t - 1];
    for (int j = 0; j < CH; j++) {
        int idx = base + j;
        if (idx < Nn) { d_off[idx] = run; run += d_cnt[idx]; }
    }
    if (t == 1023) d_off[Nn] = run;
}

__global__ void k_scatter(const int* __restrict__ src, const int* __restrict__ dst,
                          const float* __restrict__ pseudo) {
    int e = blockIdx.x * blockDim.x + threadIdx.x;
    if (e >= Ee) return;
    int d = dst[e];
    int pos = d_off[d] + atomicAdd(&d_cur[d], 1);
    float v0 = pseudo[2 * e] * 4.f;
    float v1 = pseudo[2 * e + 1] * 4.f;
    int lo0 = __float2int_rd(v0); lo0 = lo0 < 0 ? 0 : (lo0 > 3 ? 3 : lo0);
    int lo1 = __float2int_rd(v1); lo1 = lo1 < 0 ? 0 : (lo1 > 3 ? 3 : lo1);
    float f0 = v0 - (float)lo0, f1 = v1 - (float)lo1;
    float g0 = 1.f - f0, g1 = 1.f - f1;
    int k0 = lo0 * 5 + lo1;
    int wx = k0 | ((k0 + 1) << 8) | ((k0 + 5) << 16) | ((k0 + 6) << 24);
    *(float4*)&d_edge[pos].basis = make_float4(g0 * g1, g0 * f1, f0 * g1, f0 * f1);
    *(int4*)&d_edge[pos].src = make_int4(src[e], wx, 0, 0);
}

// ---------------- weight prep (fold root into GEMM weights) ----------------
__global__ void k_wprep(const float* __restrict__ W1, const float* __restrict__ root1,
                        const float* __restrict__ W2, const float* __restrict__ root2) {
    int j = blockIdx.x * blockDim.x + threadIdx.x;
    if (j < 192 * 32) {
        float v = 0.f;
        if (j < 5600) v = W1[j];
        else if (j < 5824) v = root1[j - 5600];
        d_W1p[j] = v;
    }
    if (j < 832 * 64) {
        float v;
        if (j < 51200) v = W2[j];
        else v = root2[j - 51200];
        d_W2p[j] = v;
    }
}

// ---------------- U1 build ----------------
__global__ void k_u1(const float* __restrict__ x) {
    __shared__ float su[8][4][176];
    int tid = threadIdx.x;
    int warp = tid >> 5, lane = tid & 31;
    int n = blockIdx.x * 8 + warp;
    if (n >= Nn) return;
    float(*u)[176] = su[warp];
    for (int j = lane; j < 4 * 176; j += 32) ((float*)u)[j] = 0.f;
    __syncwarp();
    int beg = d_off[n], end = d_off[n + 1];
    int eb = lane / 7, i = lane - eb * 7;
    if (lane < 28) {
        for (int p0 = beg; p0 < end; p0 += 4) {
            int p = p0 + eb;
            if (p < end) {
                float4 bs = *(const float4*)&d_edge[p].basis;
                int2 sw = *(const int2*)&d_edge[p].src;
                int sv = sw.x, wx = sw.y;
                float xv = x[sv * 7 + i];
                u[eb][(wx & 255) * 7 + i]         += bs.x * xv;
                u[eb][((wx >> 8) & 255) * 7 + i]  += bs.y * xv;
                u[eb][((wx >> 16) & 255) * 7 + i] += bs.z * xv;
                u[eb][((wx >> 24) & 255) * 7 + i] += bs.w * xv;
            }
        }
    }
    __syncwarp();
    float inv = 1.f / fmaxf((float)(end - beg), 1.f);
    for (int j = lane; j < 192; j += 32) {
        float v;
        if (j < 175)      v = (u[0][j] + u[1][j] + u[2][j] + u[3][j]) * inv;
        else if (j < 182) v = x[n * 7 + (j - 175)];
        else              v = 0.f;
        d_U1[(size_t)n * 192 + j] = v;
    }
}

// component picker (compile-time constant c under unroll)
#define COMP(F0, F1, c) ((c) == 0 ? (F0).x : (c) == 1 ? (F0).y : (c) == 2 ? (F0).z : (c) == 3 ? (F0).w : \
                         (c) == 4 ? (F1).x : (c) == 5 ? (F1).y : (c) == 6 ? (F1).z : (F1).w)
#define COMP4(F, c) ((c) == 0 ? (F).x : (c) == 1 ? (F).y : (c) == 2 ? (F).z : (F).w)

// ---------------- GEMM1 (R1-proven): h1 = elu(U1 @ W1p + b1) ----------------
__global__ void __launch_bounds__(512) k_gemm1(const float* __restrict__ b1) {
    __shared__ float Ws[192 * 32];
    const int tid = threadIdx.x, lane = tid & 31, warp = tid >> 5;
    for (int j = tid; j < 192 * 32 / 4; j += 512)
        ((float4*)Ws)[j] = ((const float4*)d_W1p)[j];
    __syncthreads();
    const int m0 = blockIdx.x * 128 + warp * 8;
    float acc[8];
#pragma unroll
    for (int r = 0; r < 8; r++) acc[r] = 0.f;
    const int rl = lane >> 2, kl = (lane & 3) * 8;
    const float* aBase = &d_U1[(size_t)(m0 + rl) * 192 + kl];
    float4 f0 = *(const float4*)(aBase);
    float4 f1 = *(const float4*)(aBase + 4);
    for (int kb = 0; kb < 192; kb += 32) {
        float4 n0, n1;
        if (kb + 32 < 192) {
            n0 = *(const float4*)(aBase + kb + 32);
            n1 = *(const float4*)(aBase + kb + 36);
        }
#pragma unroll
        for (int kk = 0; kk < 32; kk++) {
            float w = Ws[(kb + kk) * 32 + lane];
            float srcv = COMP(f0, f1, kk & 7);
#pragma unroll
            for (int r = 0; r < 8; r++) {
                float a = __shfl_sync(0xffffffffu, srcv, (r << 2) | (kk >> 3), 32);
                acc[r] += a * w;
            }
        }
        f0 = n0; f1 = n1;
    }
    float bv = b1[lane];
#pragma unroll
    for (int r = 0; r < 8; r++)
        d_h1[(size_t)(m0 + r) * 32 + lane] = eluf(acc[r] + bv);
}

// ---------------- FUSED U2-build + GEMM2 ----------------
// Block: 512 thr, 32 nodes. Phase 1: build u[32][832] in smem (warp = 2 nodes,
// lane = channel, 1-edge prefetch). Phase 2: C[32x64] = u @ W2p, W2p streamed
// in 64-k double-buffered smem chunks, 4-way K-split, per-thread 4x4 FFMA2.
__global__ void __launch_bounds__(512) k_fused2(const float* __restrict__ b2) {
    extern __shared__ float S[];
    float* u   = S;                      // 32*832            = 26624 floats
    float* Wc  = S + 32 * 832;           // 2 * 64*64         = 8192 floats
    float* red = Wc + 2 * 64 * 64;       // 3 * 32*64         = 6144 floats
    const int tid = threadIdx.x, lane = tid & 31, warp = tid >> 5;
    const int m0 = blockIdx.x * 32;

    // ---- phase 1: build ----
    for (int j = tid; j < 32 * 832 / 4; j += 512)
        ((float4*)u)[j] = make_float4(0.f, 0.f, 0.f, 0.f);
    __syncthreads();
#pragma unroll
    for (int s = 0; s < 2; s++) {
        int node = warp * 2 + s;
        int n = m0 + node;
        float* un = u + node * 832;
        int beg = d_off[n], end = d_off[n + 1];
        float4 bs; int sv, wx; float hv;
        if (beg < end) {
            bs = *(const float4*)&d_edge[beg].basis;
            int2 sw = *(const int2*)&d_edge[beg].src;
            sv = sw.x; wx = sw.y;
            hv = d_h1[(size_t)sv * 32 + lane];
        }
        for (int p = beg; p < end; p++) {
            float4 bs_n; int sv_n = 0, wx_n = 0; float hv_n = 0.f;
            if (p + 1 < end) {
                bs_n = *(const float4*)&d_edge[p + 1].basis;
                int2 sw = *(const int2*)&d_edge[p + 1].src;
                sv_n = sw.x; wx_n = sw.y;
                hv_n = d_h1[(size_t)sv_n * 32 + lane];
            }
            un[(wx & 255) * 32 + lane]         += bs.x * hv;
            un[((wx >> 8) & 255) * 32 + lane]  += bs.y * hv;
            un[((wx >> 16) & 255) * 32 + lane] += bs.z * hv;
            un[((wx >> 24) & 255) * 32 + lane] += bs.w * hv;
            bs = bs_n; sv = sv_n; wx = wx_n; hv = hv_n;
        }
        float inv = 1.f / fmaxf((float)(end - beg), 1.f);
        for (int j = lane; j < 800; j += 32) un[j] *= inv;
        un[800 + lane] = d_h1[(size_t)n * 32 + lane];
    }
    __syncthreads();

    // ---- phase 2: GEMM ----
    const int cp = tid & 15;         // cols cp*4 .. cp*4+3
    const int rg = (tid >> 4) & 7;   // rows rg*4 .. rg*4+3
    const int ks = tid >> 7;         // K-slice 0..3 (16 k per 64-k chunk each)
    ull acc[4][2];
#pragma unroll
    for (int r = 0; r < 4; r++) { acc[r][0] = 0ULL; acc[r][1] = 0ULL; }

#define STAGEW(BUF, K0)                                                          \
    {                                                                            \
        const float4* wsrc = (const float4*)&d_W2p[(K0) * 64];                   \
        float4* wdst = (float4*)&Wc[(BUF) * 4096];                               \
        wdst[tid] = wsrc[tid];                                                   \
        wdst[tid + 512] = wsrc[tid + 512];                                       \
    }

    STAGEW(0, 0)
    __syncthreads();
    int buf = 0;
    for (int ch = 0; ch < 13; ch++) {
        if (ch + 1 < 13) { STAGEW(buf ^ 1, (ch + 1) * 64) }
        const float* Wb = &Wc[buf * 4096];
        const float* ub = &u[(rg * 4) * 832 + ch * 64 + ks * 16];
#pragma unroll
        for (int st = 0; st < 4; st++) {
            float4 a0 = *(const float4*)(ub + st * 4);
            float4 a1 = *(const float4*)(ub + 832 + st * 4);
            float4 a2 = *(const float4*)(ub + 1664 + st * 4);
            float4 a3 = *(const float4*)(ub + 2496 + st * 4);
            const float* wrow = Wb + (ks * 16 + st * 4) * 64 + cp * 4;
#pragma unroll
            for (int i = 0; i < 4; i++) {
                ulonglong2 w = *(const ulonglong2*)(wrow + i * 64);
                ull p0 = pack2(COMP4(a0, i), COMP4(a0, i));
                ull p1 = pack2(COMP4(a1, i), COMP4(a1, i));
                ull p2 = pack2(COMP4(a2, i), COMP4(a2, i));
                ull p3 = pack2(COMP4(a3, i), COMP4(a3, i));
                ffma2(acc[0][0], p0, w.x); ffma2(acc[0][1], p0, w.y);
                ffma2(acc[1][0], p1, w.x); ffma2(acc[1][1], p1, w.y);
                ffma2(acc[2][0], p2, w.x); ffma2(acc[2][1], p2, w.y);
                ffma2(acc[3][0], p3, w.x); ffma2(acc[3][1], p3, w.y);
            }
        }
        __syncthreads();
        buf ^= 1;
    }

    // ---- K-slice reduction + bias + elu + store ----
    if (ks > 0) {
        float* rb = &red[(ks - 1) * 2048];
#pragma unroll
        for (int r = 0; r < 4; r++) {
            float2 x0 = unpk(acc[r][0]);
            float2 x1 = unpk(acc[r][1]);
            *(float4*)&rb[(rg * 4 + r) * 64 + cp * 4] = make_float4(x0.x, x0.y, x1.x, x1.y);
        }
    }
    __syncthreads();
    if (ks == 0) {
        float4 bv = *(const float4*)&b2[cp * 4];
#pragma unroll
        for (int r = 0; r < 4; r++) {
            int row = rg * 4 + r;
            float2 x0 = unpk(acc[r][0]);
            float2 x1 = unpk(acc[r][1]);
            float4 v = make_float4(x0.x, x0.y, x1.x, x1.y);
            float4 p0 = *(const float4*)&red[row * 64 + cp * 4];
            float4 p1 = *(const float4*)&red[2048 + row * 64 + cp * 4];
            float4 p2 = *(const float4*)&red[4096 + row * 64 + cp * 4];
            v.x = eluf(v.x + p0.x + p1.x + p2.x + bv.x);
            v.y = eluf(v.y + p0.y + p1.y + p2.y + bv.y);
            v.z = eluf(v.z + p0.z + p1.z + p2.z + bv.z);
            v.w = eluf(v.w + p0.w + p1.w + p2.w + bv.w);
            *(float4*)&d_h2[(size_t)(m0 + row) * 64 + cp * 4] = v;
        }
    }
#undef STAGEW
}

// ---------------- pooling + FC + log_softmax ----------------
__global__ void k_head(const int* __restrict__ slices, const float* __restrict__ fcw,
                       const float* __restrict__ fcb, float* __restrict__ out) {
    int b = blockIdx.x;
    int s0 = slices[b], s1 = slices[b + 1];
    __shared__ float red[4][64];
    __shared__ float g[64];
    __shared__ float lg[30];
    int tid = threadIdx.x;  // 256
    int o = tid & 63, part = tid >> 6;
    float acc = 0.f;
    for (int n = s0 + part; n < s1; n += 4) acc += d_h2[(size_t)n * 64 + o];
    red[part][o] = acc;
    __syncthreads();
    if (part == 0) {
        float s = red[0][o] + red[1][o] + red[2][o] + red[3][o];
        g[o] = s / fmaxf((float)(s1 - s0), 1.f);
    }
    __syncthreads();
    if (tid < 30) {
        float l = fcb[tid];
        for (int i = 0; i < 64; i++) l += g[i] * fcw[i * 30 + tid];
        lg[tid] = l;
    }
    __syncthreads();
    if (tid < 30) {
        float m = -1e30f;
        for (int j = 0; j < 30; j++) m = fmaxf(m, lg[j]);
        float se = 0.f;
        for (int j = 0; j < 30; j++) se += expf(lg[j] - m);
        out[b * 30 + tid] = lg[tid] - m - logf(se);
    }
}

// ---------------- launch ----------------
extern "C" void kernel_launch(void* const* d_in, const int* in_sizes, int n_in,
                              void* d_out, int out_size) {
    const float* x      = (const float*)d_in[0];
    const int*   eidx   = (const int*)d_in[1];
    const float* pseudo = (const float*)d_in[2];
    const int*   slices = (const int*)d_in[3];
    const float* W1     = (const float*)d_in[4];
    const float* root1  = (const float*)d_in[5];
    const float* b1     = (const float*)d_in[6];
    const float* W2     = (const float*)d_in[7];
    const float* root2  = (const float*)d_in[8];
    const float* b2     = (const float*)d_in[9];
    const float* fcw    = (const float*)d_in[10];
    const float* fcb    = (const float*)d_in[11];
    float* out = (float*)d_out;

    const int* src = eidx;
    const int* dst = eidx + Ee;

    const int FUSED_SMEM = (32 * 832 + 2 * 64 * 64 + 3 * 32 * 64) * 4;  // 163840
    cudaFuncSetAttribute(k_fused2, cudaFuncAttributeMaxDynamicSharedMemorySize, FUSED_SMEM);

    k_zero<<<(Nn + 255) / 256, 256>>>();
    k_hist<<<(Ee + 1023) / 1024, 1024>>>(dst);
    k_scan<<<1, 1024>>>();
    k_scatter<<<(Ee + 1023) / 1024, 1024>>>(src, dst, pseudo);
    k_wprep<<<(832 * 64 + 255) / 256, 256>>>(W1, root1, W2, root2);
    k_u1<<<Nn / 8, 256>>>(x);
    k_gemm1<<<Nn / 128, 512>>>(b1);
    k_fused2<<<Nn / 32, 512, FUSED_SMEM>>>(b2);
    k_head<<<Bb, 256>>>(slices, fcw, fcb, out);
}

// round 6
// speedup vs baseline: 1.2529x; 1.2529x over previous
#include <cuda_runtime.h>
#include <cuda_fp16.h>
#include <math.h>
#include <stdint.h>

#define Nn 51200
#define Ee 819200
#define Bb 64

typedef unsigned long long ull;

// ---------------- scratch (__device__ globals; allocation-free) ----------------
struct __align__(32) EdgeRec { float4 basis; int src; int widx; int p0; int p1; };

__device__ int     d_cnt[Nn];
__device__ int     d_cur[Nn];
__device__ int     d_off[Nn + 1];
__device__ EdgeRec d_edge[Ee];
__device__ float   d_W1p[192 * 32];          // rows 0..174 = W1 flat, 175..181 = root1, rest 0
__device__ float   d_W2p[832 * 64];          // rows 0..799 = W2 flat, 800..831 = root2
__device__ __half  d_U1h[(size_t)Nn * 192];
__device__ float   d_h1[(size_t)Nn * 32];
__device__ __half  d_U2h[(size_t)Nn * 832];
__device__ float   d_h2[(size_t)Nn * 64];

__device__ __forceinline__ float eluf(float v) { return v > 0.f ? v : (expf(v) - 1.f); }

__device__ __forceinline__ void ffma2(ull& d, ull a, ull b) {
    asm("fma.rn.f32x2 %0, %1, %2, %0;" : "+l"(d) : "l"(a), "l"(b));
}
__device__ __forceinline__ ull pack2(float x, float y) {
    ull r;
    asm("mov.b64 %0, {%1, %2};" : "=l"(r) : "f"(x), "f"(y));
    return r;
}
__device__ __forceinline__ float2 unpk(ull v) {
    float2 r;
    asm("mov.b64 {%0,%1}, %2;" : "=f"(r.x), "=f"(r.y) : "l"(v));
    return r;
}

// ---------------- CSR build ----------------
__global__ void k_zero() {
    int i = blockIdx.x * blockDim.x + threadIdx.x;
    if (i < Nn) { d_cnt[i] = 0; d_cur[i] = 0; }
}

__global__ void k_hist(const int* __restrict__ dst) {
    int e = blockIdx.x * blockDim.x + threadIdx.x;
    if (e < Ee) atomicAdd(&d_cnt[dst[e]], 1);
}

__global__ void k_scan() {
    __shared__ int s[1024];
    int t = threadIdx.x;
    const int CH = (Nn + 1023) / 1024;  // 50
    int base = t * CH;
    int sum = 0;
    for (int j = 0; j < CH; j++) {
        int idx = base + j;
        if (idx < Nn) sum += d_cnt[idx];
    }
    s[t] = sum;
    __syncthreads();
    for (int ofs = 1; ofs < 1024; ofs <<= 1) {
        int v = (t >= ofs) ? s[t - ofs] : 0;
        __syncthreads();
        if (t >= ofs) s[t] += v;
        __syncthreads();
    }
    int run = (t == 0) ? 0 : s[t - 1];
    for (int j = 0; j < CH; j++) {
        int idx = base + j;
        if (idx < Nn) { d_off[idx] = run; run += d_cnt[idx]; }
    }
    if (t == 1023) d_off[Nn] = run;
}

__global__ void k_scatter(const int* __restrict__ src, const int* __restrict__ dst,
                          const float* __restrict__ pseudo) {
    int e = blockIdx.x * blockDim.x + threadIdx.x;
    if (e >= Ee) return;
    int d = dst[e];
    int pos = d_off[d] + atomicAdd(&d_cur[d], 1);
    float v0 = pseudo[2 * e] * 4.f;
    float v1 = pseudo[2 * e + 1] * 4.f;
    int lo0 = __float2int_rd(v0); lo0 = lo0 < 0 ? 0 : (lo0 > 3 ? 3 : lo0);
    int lo1 = __float2int_rd(v1); lo1 = lo1 < 0 ? 0 : (lo1 > 3 ? 3 : lo1);
    float f0 = v0 - (float)lo0, f1 = v1 - (float)lo1;
    float g0 = 1.f - f0, g1 = 1.f - f1;
    int k0 = lo0 * 5 + lo1;
    int wx = k0 | ((k0 + 1) << 8) | ((k0 + 5) << 16) | ((k0 + 6) << 24);
    *(float4*)&d_edge[pos].basis = make_float4(g0 * g1, g0 * f1, f0 * g1, f0 * f1);
    *(int4*)&d_edge[pos].src = make_int4(src[e], wx, 0, 0);
}

// ---------------- weight prep (fold root into GEMM weights) ----------------
__global__ void k_wprep(const float* __restrict__ W1, const float* __restrict__ root1,
                        const float* __restrict__ W2, const float* __restrict__ root2) {
    int j = blockIdx.x * blockDim.x + threadIdx.x;
    if (j < 192 * 32) {
        float v = 0.f;
        if (j < 5600) v = W1[j];
        else if (j < 5824) v = root1[j - 5600];
        d_W1p[j] = v;
    }
    if (j < 832 * 64) {
        float v;
        if (j < 51200) v = W2[j];
        else v = root2[j - 51200];
        d_W2p[j] = v;
    }
}

// ---------------- U1 build (fp16 output) ----------------
__global__ void k_u1(const float* __restrict__ x) {
    __shared__ float su[8][4][176];
    int tid = threadIdx.x;
    int warp = tid >> 5, lane = tid & 31;
    int n = blockIdx.x * 8 + warp;
    if (n >= Nn) return;
    float(*u)[176] = su[warp];
    for (int j = lane; j < 4 * 176; j += 32) ((float*)u)[j] = 0.f;
    __syncwarp();
    int beg = d_off[n], end = d_off[n + 1];
    int eb = lane / 7, i = lane - eb * 7;
    if (lane < 28) {
        for (int p0 = beg; p0 < end; p0 += 4) {
            int p = p0 + eb;
            if (p < end) {
                float4 bs = *(const float4*)&d_edge[p].basis;
                int2 sw = *(const int2*)&d_edge[p].src;
                int sv = sw.x, wx = sw.y;
                float xv = x[sv * 7 + i];
                u[eb][(wx & 255) * 7 + i]         += bs.x * xv;
                u[eb][((wx >> 8) & 255) * 7 + i]  += bs.y * xv;
                u[eb][((wx >> 16) & 255) * 7 + i] += bs.z * xv;
                u[eb][((wx >> 24) & 255) * 7 + i] += bs.w * xv;
            }
        }
    }
    __syncwarp();
    float inv = 1.f / fmaxf((float)(end - beg), 1.f);
    __half2* out = (__half2*)&d_U1h[(size_t)n * 192];
    for (int j2 = lane; j2 < 96; j2 += 32) {
        float v[2];
#pragma unroll
        for (int t = 0; t < 2; t++) {
            int j = 2 * j2 + t;
            if (j < 175)      v[t] = (u[0][j] + u[1][j] + u[2][j] + u[3][j]) * inv;
            else if (j < 182) v[t] = x[n * 7 + (j - 175)];
            else              v[t] = 0.f;
        }
        out[j2] = __floats2half2_rn(v[0], v[1]);
    }
}

// ---------------- U2 build (fp16 output, 1-edge prefetch) ----------------
__global__ void k_u2() {
    __shared__ float su[8][800];
    int tid = threadIdx.x;
    int warp = tid >> 5, lane = tid & 31;
    int n = blockIdx.x * 8 + warp;
    if (n >= Nn) return;
    float* u = su[warp];
    for (int j = lane; j < 800; j += 32) u[j] = 0.f;
    __syncwarp();
    int beg = d_off[n], end = d_off[n + 1];
    float4 bs; int wx = 0; float hv = 0.f;
    if (beg < end) {
        bs = *(const float4*)&d_edge[beg].basis;
        int2 sw = *(const int2*)&d_edge[beg].src;
        wx = sw.y;
        hv = d_h1[(size_t)sw.x * 32 + lane];
    }
    for (int p = beg; p < end; p++) {
        float4 bs_n; int wx_n = 0; float hv_n = 0.f;
        if (p + 1 < end) {
            bs_n = *(const float4*)&d_edge[p + 1].basis;
            int2 sw = *(const int2*)&d_edge[p + 1].src;
            wx_n = sw.y;
            hv_n = d_h1[(size_t)sw.x * 32 + lane];
        }
        u[(wx & 255) * 32 + lane]         += bs.x * hv;
        u[((wx >> 8) & 255) * 32 + lane]  += bs.y * hv;
        u[((wx >> 16) & 255) * 32 + lane] += bs.z * hv;
        u[((wx >> 24) & 255) * 32 + lane] += bs.w * hv;
        bs = bs_n; wx = wx_n; hv = hv_n;
    }
    __syncwarp();
    float inv = 1.f / fmaxf((float)(end - beg), 1.f);
    __half2* out = (__half2*)&d_U2h[(size_t)n * 832];
    for (int j2 = lane; j2 < 416; j2 += 32) {
        float v[2];
#pragma unroll
        for (int t = 0; t < 2; t++) {
            int j = 2 * j2 + t;
            v[t] = (j < 800) ? u[j] * inv : d_h1[(size_t)n * 32 + (j - 800)];
        }
        out[j2] = __floats2half2_rn(v[0], v[1]);
    }
}

// ---------------- GEMM1: h1 = elu(U1h(N,192) @ W1p(192,32) + b1) ----------------
__global__ void __launch_bounds__(512) k_gemm1(const float* __restrict__ b1) {
    __shared__ float Ws[192 * 32];
    const int tid = threadIdx.x, lane = tid & 31, warp = tid >> 5;
    for (int j = tid; j < 192 * 32 / 4; j += 512)
        ((float4*)Ws)[j] = ((const float4*)d_W1p)[j];
    __syncthreads();
    const int m0 = blockIdx.x * 128 + warp * 8;
    float acc[8];
#pragma unroll
    for (int r = 0; r < 8; r++) acc[r] = 0.f;
    const int rl = lane >> 2, kl = (lane & 3) * 8;
    const __half* aBase = &d_U1h[(size_t)(m0 + rl) * 192 + kl];
    int4 raw = *(const int4*)(aBase);  // 8 halfs
    for (int kb = 0; kb < 192; kb += 32) {
        int4 nraw;
        if (kb + 32 < 192) nraw = *(const int4*)(aBase + kb + 32);
        float frag[8];
        {
            const __half2* hp = (const __half2*)&raw;
#pragma unroll
            for (int i = 0; i < 4; i++) {
                float2 t = __half22float2(hp[i]);
                frag[2 * i] = t.x; frag[2 * i + 1] = t.y;
            }
        }
#pragma unroll
        for (int kk = 0; kk < 32; kk++) {
            float w = Ws[(kb + kk) * 32 + lane];
            float srcv = frag[kk & 7];
#pragma unroll
            for (int r = 0; r < 8; r++) {
                float a = __shfl_sync(0xffffffffu, srcv, (r << 2) | (kk >> 3), 32);
                acc[r] += a * w;
            }
        }
        raw = nraw;
    }
    float bv = b1[lane];
#pragma unroll
    for (int r = 0; r < 8; r++)
        d_h1[(size_t)(m0 + r) * 32 + lane] = eluf(acc[r] + bv);
}

// ---------------- GEMM2: h2 = elu(U2h(N,832) @ W2p(832,64) + b2) ----------------
// 256 thr (8 warps), tile 128x64. A fragments fp16->fp32 in regs + shfl,
// W double-buffered smem, FFMA2.
__global__ void __launch_bounds__(256) k_gemm2(const float* __restrict__ b2) {
    __shared__ float4 Wt[2][512];   // [32 k][64 cols] per buffer
    const int tid = threadIdx.x, lane = tid & 31, warp = tid >> 5;
    const int rg = lane >> 4, cg = lane & 15;
    const int m0 = blockIdx.x * 128;
    const int myrow = m0 + warp * 16 + (lane >> 1);
    const __half* aRow = &d_U2h[(size_t)myrow * 832 + (lane & 1) * 16];

    ull acc[8][2];
#pragma unroll
    for (int j = 0; j < 8; j++) { acc[j][0] = 0ULL; acc[j][1] = 0ULL; }

    int4 raw0 = *(const int4*)(aRow);       // halfs 0..7
    int4 raw1 = *(const int4*)(aRow + 8);   // halfs 8..15
    Wt[0][tid]       = ((const float4*)d_W2p)[tid];
    Wt[0][tid + 256] = ((const float4*)d_W2p)[tid + 256];
    __syncthreads();

    int buf = 0;
    for (int kb = 0; kb < 832; kb += 32) {
        int4 n0, n1;
        if (kb + 32 < 832) {
            n0 = *(const int4*)(aRow + kb + 32);
            n1 = *(const int4*)(aRow + kb + 40);
            const float4* wsrc = (const float4*)&d_W2p[(kb + 32) * 64];
            Wt[buf ^ 1][tid]       = wsrc[tid];
            Wt[buf ^ 1][tid + 256] = wsrc[tid + 256];
        }
        float frag[16];
        {
            const __half2* hp0 = (const __half2*)&raw0;
            const __half2* hp1 = (const __half2*)&raw1;
#pragma unroll
            for (int i = 0; i < 4; i++) {
                float2 t0 = __half22float2(hp0[i]);
                float2 t1 = __half22float2(hp1[i]);
                frag[2 * i] = t0.x; frag[2 * i + 1] = t0.y;
                frag[8 + 2 * i] = t1.x; frag[9 + 2 * i] = t1.y;
            }
        }
        const float* wb = (const float*)&Wt[buf][0];
#pragma unroll
        for (int kk = 0; kk < 32; kk++) {
            float fv = frag[kk & 15];
            ulonglong2 w = *(const ulonglong2*)(wb + kk * 64 + cg * 4);
            const int half = (kk >> 4);
#pragma unroll
            for (int j = 0; j < 8; j++) {
                float a = __shfl_sync(0xffffffffu, fv, ((rg * 8 + j) << 1) | half, 32);
                ull a2 = pack2(a, a);
                ffma2(acc[j][0], a2, w.x);
                ffma2(acc[j][1], a2, w.y);
            }
        }
        __syncthreads();
        buf ^= 1;
        raw0 = n0; raw1 = n1;
    }

    float4 bv = *(const float4*)&b2[cg * 4];
#pragma unroll
    for (int j = 0; j < 8; j++) {
        int row = m0 + warp * 16 + rg * 8 + j;
        float2 p0 = unpk(acc[j][0]);
        float2 p1 = unpk(acc[j][1]);
        float4 o = make_float4(eluf(p0.x + bv.x), eluf(p0.y + bv.y),
                               eluf(p1.x + bv.z), eluf(p1.y + bv.w));
        *(float4*)&d_h2[(size_t)row * 64 + cg * 4] = o;
    }
}

// ---------------- pooling + FC + log_softmax ----------------
__global__ void k_head(const int* __restrict__ slices, const float* __restrict__ fcw,
                       const float* __restrict__ fcb, float* __restrict__ out) {
    int b = blockIdx.x;
    int s0 = slices[b], s1 = slices[b + 1];
    __shared__ float red[4][64];
    __shared__ float g[64];
    __shared__ float lg[30];
    int tid = threadIdx.x;  // 256
    int o = tid & 63, part = tid >> 6;
    float acc = 0.f;
    for (int n = s0 + part; n < s1; n += 4) acc += d_h2[(size_t)n * 64 + o];
    red[part][o] = acc;
    __syncthreads();
    if (part == 0) {
        float s = red[0][o] + red[1][o] + red[2][o] + red[3][o];
        g[o] = s / fmaxf((float)(s1 - s0), 1.f);
    }
    __syncthreads();
    if (tid < 30) {
        float l = fcb[tid];
        for (int i = 0; i < 64; i++) l += g[i] * fcw[i * 30 + tid];
        lg[tid] = l;
    }
    __syncthreads();
    if (tid < 30) {
        float m = -1e30f;
        for (int j = 0; j < 30; j++) m = fmaxf(m, lg[j]);
        float se = 0.f;
        for (int j = 0; j < 30; j++) se += expf(lg[j] - m);
        out[b * 30 + tid] = lg[tid] - m - logf(se);
    }
}

// ---------------- launch ----------------
extern "C" void kernel_launch(void* const* d_in, const int* in_sizes, int n_in,
                              void* d_out, int out_size) {
    const float* x      = (const float*)d_in[0];
    const int*   eidx   = (const int*)d_in[1];
    const float* pseudo = (const float*)d_in[2];
    const int*   slices = (const int*)d_in[3];
    const float* W1     = (const float*)d_in[4];
    const float* root1  = (const float*)d_in[5];
    const float* b1     = (const float*)d_in[6];
    const float* W2     = (const float*)d_in[7];
    const float* root2  = (const float*)d_in[8];
    const float* b2     = (const float*)d_in[9];
    const float* fcw    = (const float*)d_in[10];
    const float* fcb    = (const float*)d_in[11];
    float* out = (float*)d_out;

    const int* src = eidx;
    const int* dst = eidx + Ee;

    k_zero<<<(Nn + 255) / 256, 256>>>();
    k_hist<<<(Ee + 1023) / 1024, 1024>>>(dst);
    k_scan<<<1, 1024>>>();
    k_scatter<<<(Ee + 1023) / 1024, 1024>>>(src, dst, pseudo);
    k_wprep<<<(832 * 64 + 255) / 256, 256>>>(W1, root1, W2, root2);
    k_u1<<<Nn / 8, 256>>>(x);
    k_gemm1<<<Nn / 128, 512>>>(b1);
    k_u2<<<Nn / 8, 256>>>();
    k_gemm2<<<Nn / 128, 256>>>(b2);
    k_head<<<Bb, 256>>>(slices, fcw, fcb, out);
}

// round 7
// speedup vs baseline: 1.7331x; 1.3833x over previous
#include <cuda_runtime.h>
#include <cuda_fp16.h>
#include <math.h>
#include <stdint.h>

#define Nn 51200
#define Ee 819200
#define Bb 64

typedef unsigned long long ull;

// ---------------- scratch (__device__ globals; allocation-free) ----------------
struct __align__(32) EdgeRec { float4 basis; int src; int widx; int p0; int p1; };

__device__ int     d_cnt[Nn];
__device__ int     d_cur[Nn];
__device__ int     d_off[Nn + 1];
__device__ EdgeRec d_edge[Ee];
__device__ float   d_W1p[192 * 32];          // rows 0..174 = W1 flat, 175..181 = root1, rest 0
__device__ __half  d_W2ph[832 * 64];         // fp16 W2 (rows 0..799 = W2, 800..831 = root2)
__device__ __half  d_U1h[(size_t)Nn * 192];
__device__ float   d_h1[(size_t)Nn * 32];
__device__ __half  d_U2h[(size_t)Nn * 832];
__device__ float   d_h2[(size_t)Nn * 64];

__device__ __forceinline__ float eluf(float v) { return v > 0.f ? v : (expf(v) - 1.f); }

// ---------------- mma helpers ----------------
__device__ __forceinline__ void ldmA4(uint32_t* a, uint32_t addr) {
    asm volatile("ldmatrix.sync.aligned.m8n8.x4.shared.b16 {%0,%1,%2,%3}, [%4];"
                 : "=r"(a[0]), "=r"(a[1]), "=r"(a[2]), "=r"(a[3]) : "r"(addr));
}
__device__ __forceinline__ void ldmBT4(uint32_t* b, uint32_t addr) {
    asm volatile("ldmatrix.sync.aligned.m8n8.x4.trans.shared.b16 {%0,%1,%2,%3}, [%4];"
                 : "=r"(b[0]), "=r"(b[1]), "=r"(b[2]), "=r"(b[3]) : "r"(addr));
}
__device__ __forceinline__ void mma16816(float* c, const uint32_t* a, uint32_t b0, uint32_t b1) {
    asm volatile(
        "mma.sync.aligned.m16n8k16.row.col.f32.f16.f16.f32 "
        "{%0,%1,%2,%3}, {%4,%5,%6,%7}, {%8,%9}, {%0,%1,%2,%3};"
        : "+f"(c[0]), "+f"(c[1]), "+f"(c[2]), "+f"(c[3])
        : "r"(a[0]), "r"(a[1]), "r"(a[2]), "r"(a[3]), "r"(b0), "r"(b1));
}

// ---------------- CSR build ----------------
__global__ void k_zero() {
    int i = blockIdx.x * blockDim.x + threadIdx.x;
    if (i < Nn) { d_cnt[i] = 0; d_cur[i] = 0; }
}

__global__ void k_hist(const int* __restrict__ dst) {
    int e = blockIdx.x * blockDim.x + threadIdx.x;
    if (e < Ee) atomicAdd(&d_cnt[dst[e]], 1);
}

__global__ void k_scan() {
    __shared__ int s[1024];
    int t = threadIdx.x;
    const int CH = (Nn + 1023) / 1024;  // 50
    int base = t * CH;
    int sum = 0;
    for (int j = 0; j < CH; j++) {
        int idx = base + j;
        if (idx < Nn) sum += d_cnt[idx];
    }
    s[t] = sum;
    __syncthreads();
    for (int ofs = 1; ofs < 1024; ofs <<= 1) {
        int v = (t >= ofs) ? s[t - ofs] : 0;
        __syncthreads();
        if (t >= ofs) s[t] += v;
        __syncthreads();
    }
    int run = (t == 0) ? 0 : s[t - 1];
    for (int j = 0; j < CH; j++) {
        int idx = base + j;
        if (idx < Nn) { d_off[idx] = run; run += d_cnt[idx]; }
    }
    if (t == 1023) d_off[Nn] = run;
}

__global__ void k_scatter(const int* __restrict__ src, const int* __restrict__ dst,
                          const float* __restrict__ pseudo) {
    int e = blockIdx.x * blockDim.x + threadIdx.x;
    if (e >= Ee) return;
    int d = dst[e];
    int pos = d_off[d] + atomicAdd(&d_cur[d], 1);
    float v0 = pseudo[2 * e] * 4.f;
    float v1 = pseudo[2 * e + 1] * 4.f;
    int lo0 = __float2int_rd(v0); lo0 = lo0 < 0 ? 0 : (lo0 > 3 ? 3 : lo0);
    int lo1 = __float2int_rd(v1); lo1 = lo1 < 0 ? 0 : (lo1 > 3 ? 3 : lo1);
    float f0 = v0 - (float)lo0, f1 = v1 - (float)lo1;
    float g0 = 1.f - f0, g1 = 1.f - f1;
    int k0 = lo0 * 5 + lo1;
    int wx = k0 | ((k0 + 1) << 8) | ((k0 + 5) << 16) | ((k0 + 6) << 24);
    *(float4*)&d_edge[pos].basis = make_float4(g0 * g1, g0 * f1, f0 * g1, f0 * f1);
    *(int4*)&d_edge[pos].src = make_int4(src[e], wx, 0, 0);
}

// ---------------- weight prep ----------------
__global__ void k_wprep(const float* __restrict__ W1, const float* __restrict__ root1,
                        const float* __restrict__ W2, const float* __restrict__ root2) {
    int j = blockIdx.x * blockDim.x + threadIdx.x;
    if (j < 192 * 32) {
        float v = 0.f;
        if (j < 5600) v = W1[j];
        else if (j < 5824) v = root1[j - 5600];
        d_W1p[j] = v;
    }
    if (j < 832 * 64) {
        float v;
        if (j < 51200) v = W2[j];
        else v = root2[j - 51200];
        d_W2ph[j] = __float2half_rn(v);
    }
}

// ---------------- U1 build (fp16 output) ----------------
__global__ void k_u1(const float* __restrict__ x) {
    __shared__ float su[8][4][176];
    int tid = threadIdx.x;
    int warp = tid >> 5, lane = tid & 31;
    int n = blockIdx.x * 8 + warp;
    if (n >= Nn) return;
    float(*u)[176] = su[warp];
    for (int j = lane; j < 4 * 176; j += 32) ((float*)u)[j] = 0.f;
    __syncwarp();
    int beg = d_off[n], end = d_off[n + 1];
    int eb = lane / 7, i = lane - eb * 7;
    if (lane < 28) {
        for (int p0 = beg; p0 < end; p0 += 4) {
            int p = p0 + eb;
            if (p < end) {
                float4 bs = *(const float4*)&d_edge[p].basis;
                int2 sw = *(const int2*)&d_edge[p].src;
                int sv = sw.x, wx = sw.y;
                float xv = x[sv * 7 + i];
                u[eb][(wx & 255) * 7 + i]         += bs.x * xv;
                u[eb][((wx >> 8) & 255) * 7 + i]  += bs.y * xv;
                u[eb][((wx >> 16) & 255) * 7 + i] += bs.z * xv;
                u[eb][((wx >> 24) & 255) * 7 + i] += bs.w * xv;
            }
        }
    }
    __syncwarp();
    float inv = 1.f / fmaxf((float)(end - beg), 1.f);
    __half2* out = (__half2*)&d_U1h[(size_t)n * 192];
    for (int j2 = lane; j2 < 96; j2 += 32) {
        float v[2];
#pragma unroll
        for (int t = 0; t < 2; t++) {
            int j = 2 * j2 + t;
            if (j < 175)      v[t] = (u[0][j] + u[1][j] + u[2][j] + u[3][j]) * inv;
            else if (j < 182) v[t] = x[n * 7 + (j - 175)];
            else              v[t] = 0.f;
        }
        out[j2] = __floats2half2_rn(v[0], v[1]);
    }
}

// ---------------- U2 build (fp16 output, 1-edge prefetch) ----------------
__global__ void k_u2() {
    __shared__ float su[8][800];
    int tid = threadIdx.x;
    int warp = tid >> 5, lane = tid & 31;
    int n = blockIdx.x * 8 + warp;
    if (n >= Nn) return;
    float* u = su[warp];
    for (int j = lane; j < 800; j += 32) u[j] = 0.f;
    __syncwarp();
    int beg = d_off[n], end = d_off[n + 1];
    float4 bs; int wx = 0; float hv = 0.f;
    if (beg < end) {
        bs = *(const float4*)&d_edge[beg].basis;
        int2 sw = *(const int2*)&d_edge[beg].src;
        wx = sw.y;
        hv = d_h1[(size_t)sw.x * 32 + lane];
    }
    for (int p = beg; p < end; p++) {
        float4 bs_n; int wx_n = 0; float hv_n = 0.f;
        if (p + 1 < end) {
            bs_n = *(const float4*)&d_edge[p + 1].basis;
            int2 sw = *(const int2*)&d_edge[p + 1].src;
            wx_n = sw.y;
            hv_n = d_h1[(size_t)sw.x * 32 + lane];
        }
        u[(wx & 255) * 32 + lane]         += bs.x * hv;
        u[((wx >> 8) & 255) * 32 + lane]  += bs.y * hv;
        u[((wx >> 16) & 255) * 32 + lane] += bs.z * hv;
        u[((wx >> 24) & 255) * 32 + lane] += bs.w * hv;
        bs = bs_n; wx = wx_n; hv = hv_n;
    }
    __syncwarp();
    float inv = 1.f / fmaxf((float)(end - beg), 1.f);
    __half2* out = (__half2*)&d_U2h[(size_t)n * 832];
    for (int j2 = lane; j2 < 416; j2 += 32) {
        float v[2];
#pragma unroll
        for (int t = 0; t < 2; t++) {
            int j = 2 * j2 + t;
            v[t] = (j < 800) ? u[j] * inv : d_h1[(size_t)n * 32 + (j - 800)];
        }
        out[j2] = __floats2half2_rn(v[0], v[1]);
    }
}

// ---------------- GEMM1: h1 = elu(U1h(N,192) @ W1p(192,32) + b1) ----------------
__global__ void __launch_bounds__(512) k_gemm1(const float* __restrict__ b1) {
    __shared__ float Ws[192 * 32];
    const int tid = threadIdx.x, lane = tid & 31, warp = tid >> 5;
    for (int j = tid; j < 192 * 32 / 4; j += 512)
        ((float4*)Ws)[j] = ((const float4*)d_W1p)[j];
    __syncthreads();
    const int m0 = blockIdx.x * 128 + warp * 8;
    float acc[8];
#pragma unroll
    for (int r = 0; r < 8; r++) acc[r] = 0.f;
    const int rl = lane >> 2, kl = (lane & 3) * 8;
    const __half* aBase = &d_U1h[(size_t)(m0 + rl) * 192 + kl];
    int4 raw = *(const int4*)(aBase);  // 8 halfs
    for (int kb = 0; kb < 192; kb += 32) {
        int4 nraw;
        if (kb + 32 < 192) nraw = *(const int4*)(aBase + kb + 32);
        float frag[8];
        {
            const __half2* hp = (const __half2*)&raw;
#pragma unroll
            for (int i = 0; i < 4; i++) {
                float2 t = __half22float2(hp[i]);
                frag[2 * i] = t.x; frag[2 * i + 1] = t.y;
            }
        }
#pragma unroll
        for (int kk = 0; kk < 32; kk++) {
            float w = Ws[(kb + kk) * 32 + lane];
            float srcv = frag[kk & 7];
#pragma unroll
            for (int r = 0; r < 8; r++) {
                float a = __shfl_sync(0xffffffffu, srcv, (r << 2) | (kk >> 3), 32);
                acc[r] += a * w;
            }
        }
        raw = nraw;
    }
    float bv = b1[lane];
#pragma unroll
    for (int r = 0; r < 8; r++)
        d_h1[(size_t)(m0 + r) * 32 + lane] = eluf(acc[r] + bv);
}

// ---------------- GEMM2 (tensor cores): h2 = elu(U2h @ W2ph + b2) ----------------
// 256 thr (8 warps). Tile M=128 x N=64, K in 13 chunks of 64 (double-buffered).
// Warp w: rows 16w..16w+15, all 64 cols; 8 mma m16n8k16 per 16-k step.
// smem rows padded to 72 halfs (144 B) -> ldmatrix conflict-free.
#define APITCH 72
#define ABUF (128 * APITCH)
#define WBUF (64 * APITCH)
__global__ void __launch_bounds__(256) k_gemm2t(const float* __restrict__ b2) {
    extern __shared__ __half S[];
    __half* Asm = S;                 // [2][128][72]
    __half* Wsm = S + 2 * ABUF;      // [2][64][72]
    const int tid = threadIdx.x, lane = tid & 31, warp = tid >> 5;
    const int m0 = blockIdx.x * 128;

    // staging indices
    const int arow = tid >> 1, ahalf = tid & 1;        // A: 2 thr/row, 32 halfs each
    const int wrow = tid >> 2, wseg = (tid & 3) * 16;  // W: 4 thr/row, 16 halfs each
    const __half* aSrc = &d_U2h[(size_t)(m0 + arow) * 832 + ahalf * 32];
    const __half* wSrc = &d_W2ph[wrow * 64 + wseg];

    float acc[8][4];
#pragma unroll
    for (int i = 0; i < 8; i++)
#pragma unroll
        for (int j = 0; j < 4; j++) acc[i][j] = 0.f;

    // stage chunk 0
    {
        int4 a0 = *(const int4*)(aSrc);
        int4 a1 = *(const int4*)(aSrc + 8);
        int4 a2 = *(const int4*)(aSrc + 16);
        int4 a3 = *(const int4*)(aSrc + 24);
        __half* ad = &Asm[arow * APITCH + ahalf * 32];
        ((int4*)ad)[0] = a0; ((int4*)ad)[1] = a1;
        ((int4*)ad)[2] = a2; ((int4*)ad)[3] = a3;
        int4 w0 = *(const int4*)(wSrc);
        int4 w1 = *(const int4*)(wSrc + 8);
        __half* wd = &Wsm[wrow * APITCH + wseg];
        ((int4*)wd)[0] = w0; ((int4*)wd)[1] = w1;
    }
    __syncthreads();

    // ldmatrix base offsets (lane-dependent)
    const int aLdRow = lane & 15, aLdColGrp = (lane >> 4) * 8;
    const int bLdRow = (lane & 7) + 8 * ((lane >> 3) & 1), bLdColGrp = (lane >> 4) * 8;

    int buf = 0;
    for (int ch = 0; ch < 13; ch++) {
        // prefetch next chunk to regs
        int4 pa0, pa1, pa2, pa3, pw0, pw1;
        if (ch + 1 < 13) {
            const __half* as = aSrc + (ch + 1) * 64;
            pa0 = *(const int4*)(as);
            pa1 = *(const int4*)(as + 8);
            pa2 = *(const int4*)(as + 16);
            pa3 = *(const int4*)(as + 24);
            const __half* ws = wSrc + (size_t)(ch + 1) * 64 * 64;
            pw0 = *(const int4*)(ws);
            pw1 = *(const int4*)(ws + 8);
        }
        const __half* Ab = &Asm[buf * ABUF];
        const __half* Wb = &Wsm[buf * WBUF];
#pragma unroll
        for (int ks = 0; ks < 4; ks++) {
            uint32_t a[4];
            uint32_t aAddr = (uint32_t)__cvta_generic_to_shared(
                &Ab[(warp * 16 + aLdRow) * APITCH + ks * 16 + aLdColGrp]);
            ldmA4(a, aAddr);
#pragma unroll
            for (int nb = 0; nb < 4; nb++) {
                uint32_t b[4];
                uint32_t bAddr = (uint32_t)__cvta_generic_to_shared(
                    &Wb[(ks * 16 + bLdRow) * APITCH + nb * 16 + bLdColGrp]);
                ldmBT4(b, bAddr);
                mma16816(acc[2 * nb],     a, b[0], b[1]);
                mma16816(acc[2 * nb + 1], a, b[2], b[3]);
            }
        }
        // store prefetched chunk to alternate buffer
        if (ch + 1 < 13) {
            __half* ad = &Asm[(buf ^ 1) * ABUF + arow * APITCH + ahalf * 32];
            ((int4*)ad)[0] = pa0; ((int4*)ad)[1] = pa1;
            ((int4*)ad)[2] = pa2; ((int4*)ad)[3] = pa3;
            __half* wd = &Wsm[(buf ^ 1) * WBUF + wrow * APITCH + wseg];
            ((int4*)wd)[0] = pw0; ((int4*)wd)[1] = pw1;
        }
        __syncthreads();
        buf ^= 1;
    }

    // epilogue: lane holds rows g=lane>>2 (+8), cols tig*2 (+1) per 8-col block
    const int g = lane >> 2, tig = lane & 3;
#pragma unroll
    for (int nb = 0; nb < 4; nb++) {
        int c0 = nb * 16 + tig * 2;
        int c1 = nb * 16 + 8 + tig * 2;
        float2 bv0 = *(const float2*)&b2[c0];
        float2 bv1 = *(const float2*)&b2[c1];
        int rowA = m0 + warp * 16 + g;
        int rowB = rowA + 8;
        float* hA = &d_h2[(size_t)rowA * 64];
        float* hB = &d_h2[(size_t)rowB * 64];
        *(float2*)&hA[c0] = make_float2(eluf(acc[2 * nb][0] + bv0.x), eluf(acc[2 * nb][1] + bv0.y));
        *(float2*)&hB[c0] = make_float2(eluf(acc[2 * nb][2] + bv0.x), eluf(acc[2 * nb][3] + bv0.y));
        *(float2*)&hA[c1] = make_float2(eluf(acc[2 * nb + 1][0] + bv1.x), eluf(acc[2 * nb + 1][1] + bv1.y));
        *(float2*)&hB[c1] = make_float2(eluf(acc[2 * nb + 1][2] + bv1.x), eluf(acc[2 * nb + 1][3] + bv1.y));
    }
}

// ---------------- pooling + FC + log_softmax ----------------
__global__ void k_head(const int* __restrict__ slices, const float* __restrict__ fcw,
                       const float* __restrict__ fcb, float* __restrict__ out) {
    int b = blockIdx.x;
    int s0 = slices[b], s1 = slices[b + 1];
    __shared__ float red[4][64];
    __shared__ float g[64];
    __shared__ float lg[30];
    int tid = threadIdx.x;  // 256
    int o = tid & 63, part = tid >> 6;
    float acc = 0.f;
    for (int n = s0 + part; n < s1; n += 4) acc += d_h2[(size_t)n * 64 + o];
    red[part][o] = acc;
    __syncthreads();
    if (part == 0) {
        float s = red[0][o] + red[1][o] + red[2][o] + red[3][o];
        g[o] = s / fmaxf((float)(s1 - s0), 1.f);
    }
    __syncthreads();
    if (tid < 30) {
        float l = fcb[tid];
        for (int i = 0; i < 64; i++) l += g[i] * fcw[i * 30 + tid];
        lg[tid] = l;
    }
    __syncthreads();
    if (tid < 30) {
        float m = -1e30f;
        for (int j = 0; j < 30; j++) m = fmaxf(m, lg[j]);
        float se = 0.f;
        for (int j = 0; j < 30; j++) se += expf(lg[j] - m);
        out[b * 30 + tid] = lg[tid] - m - logf(se);
    }
}

// ---------------- launch ----------------
extern "C" void kernel_launch(void* const* d_in, const int* in_sizes, int n_in,
                              void* d_out, int out_size) {
    const float* x      = (const float*)d_in[0];
    const int*   eidx   = (const int*)d_in[1];
    const float* pseudo = (const float*)d_in[2];
    const int*   slices = (const int*)d_in[3];
    const float* W1     = (const float*)d_in[4];
    const float* root1  = (const float*)d_in[5];
    const float* b1     = (const float*)d_in[6];
    const float* W2     = (const float*)d_in[7];
    const float* root2  = (const float*)d_in[8];
    const float* b2     = (const float*)d_in[9];
    const float* fcw    = (const float*)d_in[10];
    const float* fcb    = (const float*)d_in[11];
    float* out = (float*)d_out;

    const int* src = eidx;
    const int* dst = eidx + Ee;

    const int G2_SMEM = (2 * ABUF + 2 * WBUF) * 2;  // bytes (halfs*2) = 55296
    cudaFuncSetAttribute(k_gemm2t, cudaFuncAttributeMaxDynamicSharedMemorySize, G2_SMEM);

    k_zero<<<(Nn + 255) / 256, 256>>>();
    k_hist<<<(Ee + 1023) / 1024, 1024>>>(dst);
    k_scan<<<1, 1024>>>();
    k_scatter<<<(Ee + 1023) / 1024, 1024>>>(src, dst, pseudo);
    k_wprep<<<(832 * 64 + 255) / 256, 256>>>(W1, root1, W2, root2);
    k_u1<<<Nn / 8, 256>>>(x);
    k_gemm1<<<Nn / 128, 512>>>(b1);
    k_u2<<<Nn / 8, 256>>>();
    k_gemm2t<<<Nn / 128, 256, G2_SMEM>>>(b2);
    k_head<<<Bb, 256>>>(slices, fcw, fcb, out);
}

// round 8
// speedup vs baseline: 1.9750x; 1.1396x over previous
#include <cuda_runtime.h>
#include <cuda_fp16.h>
#include <math.h>
#include <stdint.h>

#define Nn 51200
#define Ee 819200
#define Bb 64

typedef unsigned long long ull;

// ---------------- scratch (__device__ globals; allocation-free) ----------------
struct __align__(32) EdgeRec { float4 basis; int src; int widx; int p0; int p1; };

__device__ int     d_cnt[Nn];
__device__ int     d_cur[Nn];
__device__ int     d_off[Nn + 1];
__device__ EdgeRec d_edge[Ee];
__device__ __half  d_W1ph[192 * 32];         // fp16 W1 (rows 0..174 = W1, 175..181 = root1, rest 0)
__device__ __half  d_W2ph[832 * 64];         // fp16 W2 (rows 0..799 = W2, 800..831 = root2)
__device__ __half  d_U1h[(size_t)Nn * 192];
__device__ float   d_h1[(size_t)Nn * 32];
__device__ __half  d_U2h[(size_t)Nn * 832];
__device__ float   d_h2[(size_t)Nn * 64];

__device__ __forceinline__ float eluf(float v) { return v > 0.f ? v : (expf(v) - 1.f); }

// ---------------- mma helpers ----------------
__device__ __forceinline__ void ldmA4(uint32_t* a, uint32_t addr) {
    asm volatile("ldmatrix.sync.aligned.m8n8.x4.shared.b16 {%0,%1,%2,%3}, [%4];"
                 : "=r"(a[0]), "=r"(a[1]), "=r"(a[2]), "=r"(a[3]) : "r"(addr));
}
__device__ __forceinline__ void ldmBT4(uint32_t* b, uint32_t addr) {
    asm volatile("ldmatrix.sync.aligned.m8n8.x4.trans.shared.b16 {%0,%1,%2,%3}, [%4];"
                 : "=r"(b[0]), "=r"(b[1]), "=r"(b[2]), "=r"(b[3]) : "r"(addr));
}
__device__ __forceinline__ void mma16816(float* c, const uint32_t* a, uint32_t b0, uint32_t b1) {
    asm volatile(
        "mma.sync.aligned.m16n8k16.row.col.f32.f16.f16.f32 "
        "{%0,%1,%2,%3}, {%4,%5,%6,%7}, {%8,%9}, {%0,%1,%2,%3};"
        : "+f"(c[0]), "+f"(c[1]), "+f"(c[2]), "+f"(c[3])
        : "r"(a[0]), "r"(a[1]), "r"(a[2]), "r"(a[3]), "r"(b0), "r"(b1));
}

// ---------------- CSR build ----------------
__global__ void k_init(const float* __restrict__ W1, const float* __restrict__ root1,
                       const float* __restrict__ W2, const float* __restrict__ root2) {
    int j = blockIdx.x * blockDim.x + threadIdx.x;
    if (j < Nn) { d_cnt[j] = 0; d_cur[j] = 0; }
    if (j < 192 * 32) {
        float v = 0.f;
        if (j < 5600) v = W1[j];
        else if (j < 5824) v = root1[j - 5600];
        d_W1ph[j] = __float2half_rn(v);
    }
    if (j < 832 * 64) {
        float v;
        if (j < 51200) v = W2[j];
        else v = root2[j - 51200];
        d_W2ph[j] = __float2half_rn(v);
    }
}

__global__ void k_hist(const int* __restrict__ dst) {
    int e = blockIdx.x * blockDim.x + threadIdx.x;
    if (e < Ee) atomicAdd(&d_cnt[dst[e]], 1);
}

__global__ void k_scan() {
    __shared__ int s[1024];
    int t = threadIdx.x;
    const int CH = (Nn + 1023) / 1024;  // 50
    int base = t * CH;
    int sum = 0;
    for (int j = 0; j < CH; j++) {
        int idx = base + j;
        if (idx < Nn) sum += d_cnt[idx];
    }
    s[t] = sum;
    __syncthreads();
    for (int ofs = 1; ofs < 1024; ofs <<= 1) {
        int v = (t >= ofs) ? s[t - ofs] : 0;
        __syncthreads();
        if (t >= ofs) s[t] += v;
        __syncthreads();
    }
    int run = (t == 0) ? 0 : s[t - 1];
    for (int j = 0; j < CH; j++) {
        int idx = base + j;
        if (idx < Nn) { d_off[idx] = run; run += d_cnt[idx]; }
    }
    if (t == 1023) d_off[Nn] = run;
}

__global__ void k_scatter(const int* __restrict__ src, const int* __restrict__ dst,
                          const float* __restrict__ pseudo) {
    int e = blockIdx.x * blockDim.x + threadIdx.x;
    if (e >= Ee) return;
    int d = dst[e];
    int pos = d_off[d] + atomicAdd(&d_cur[d], 1);
    float v0 = pseudo[2 * e] * 4.f;
    float v1 = pseudo[2 * e + 1] * 4.f;
    int lo0 = __float2int_rd(v0); lo0 = lo0 < 0 ? 0 : (lo0 > 3 ? 3 : lo0);
    int lo1 = __float2int_rd(v1); lo1 = lo1 < 0 ? 0 : (lo1 > 3 ? 3 : lo1);
    float f0 = v0 - (float)lo0, f1 = v1 - (float)lo1;
    float g0 = 1.f - f0, g1 = 1.f - f1;
    int k0 = lo0 * 5 + lo1;
    int wx = k0 | ((k0 + 1) << 8) | ((k0 + 5) << 16) | ((k0 + 6) << 24);
    *(float4*)&d_edge[pos].basis = make_float4(g0 * g1, g0 * f1, f0 * g1, f0 * f1);
    *(int4*)&d_edge[pos].src = make_int4(src[e], wx, 0, 0);
}

// ---------------- U1 build (fp16 output) ----------------
__global__ void k_u1(const float* __restrict__ x) {
    __shared__ float su[8][4][176];
    int tid = threadIdx.x;
    int warp = tid >> 5, lane = tid & 31;
    int n = blockIdx.x * 8 + warp;
    if (n >= Nn) return;
    float(*u)[176] = su[warp];
    for (int j = lane; j < 4 * 176; j += 32) ((float*)u)[j] = 0.f;
    __syncwarp();
    int beg = d_off[n], end = d_off[n + 1];
    int eb = lane / 7, i = lane - eb * 7;
    if (lane < 28) {
        for (int p0 = beg; p0 < end; p0 += 4) {
            int p = p0 + eb;
            if (p < end) {
                float4 bs = *(const float4*)&d_edge[p].basis;
                int2 sw = *(const int2*)&d_edge[p].src;
                int sv = sw.x, wx = sw.y;
                float xv = x[sv * 7 + i];
                u[eb][(wx & 255) * 7 + i]         += bs.x * xv;
                u[eb][((wx >> 8) & 255) * 7 + i]  += bs.y * xv;
                u[eb][((wx >> 16) & 255) * 7 + i] += bs.z * xv;
                u[eb][((wx >> 24) & 255) * 7 + i] += bs.w * xv;
            }
        }
    }
    __syncwarp();
    float inv = 1.f / fmaxf((float)(end - beg), 1.f);
    __half2* out = (__half2*)&d_U1h[(size_t)n * 192];
    for (int j2 = lane; j2 < 96; j2 += 32) {
        float v[2];
#pragma unroll
        for (int t = 0; t < 2; t++) {
            int j = 2 * j2 + t;
            if (j < 175)      v[t] = (u[0][j] + u[1][j] + u[2][j] + u[3][j]) * inv;
            else if (j < 182) v[t] = x[n * 7 + (j - 175)];
            else              v[t] = 0.f;
        }
        out[j2] = __floats2half2_rn(v[0], v[1]);
    }
}

// ---------------- U2 build (fp16 output, 2-edge prefetch) ----------------
__global__ void k_u2() {
    __shared__ float su[8][800];
    int tid = threadIdx.x;
    int warp = tid >> 5, lane = tid & 31;
    int n = blockIdx.x * 8 + warp;
    if (n >= Nn) return;
    float* u = su[warp];
    for (int j = lane; j < 800; j += 32) u[j] = 0.f;
    __syncwarp();
    int beg = d_off[n], end = d_off[n + 1];
    float4 bs0, bs1; int wx0 = 0, wx1 = 0; float hv0 = 0.f, hv1 = 0.f;
    if (beg < end) {
        bs0 = *(const float4*)&d_edge[beg].basis;
        int2 sw = *(const int2*)&d_edge[beg].src;
        wx0 = sw.y;
        hv0 = d_h1[(size_t)sw.x * 32 + lane];
    }
    if (beg + 1 < end) {
        bs1 = *(const float4*)&d_edge[beg + 1].basis;
        int2 sw = *(const int2*)&d_edge[beg + 1].src;
        wx1 = sw.y;
        hv1 = d_h1[(size_t)sw.x * 32 + lane];
    }
    for (int p = beg; p < end; p++) {
        float4 bs_n; int wx_n = 0; float hv_n = 0.f;
        if (p + 2 < end) {
            bs_n = *(const float4*)&d_edge[p + 2].basis;
            int2 sw = *(const int2*)&d_edge[p + 2].src;
            wx_n = sw.y;
            hv_n = d_h1[(size_t)sw.x * 32 + lane];
        }
        u[(wx0 & 255) * 32 + lane]         += bs0.x * hv0;
        u[((wx0 >> 8) & 255) * 32 + lane]  += bs0.y * hv0;
        u[((wx0 >> 16) & 255) * 32 + lane] += bs0.z * hv0;
        u[((wx0 >> 24) & 255) * 32 + lane] += bs0.w * hv0;
        bs0 = bs1; wx0 = wx1; hv0 = hv1;
        bs1 = bs_n; wx1 = wx_n; hv1 = hv_n;
    }
    __syncwarp();
    float inv = 1.f / fmaxf((float)(end - beg), 1.f);
    __half2* out = (__half2*)&d_U2h[(size_t)n * 832];
    for (int j2 = lane; j2 < 416; j2 += 32) {
        float v[2];
#pragma unroll
        for (int t = 0; t < 2; t++) {
            int j = 2 * j2 + t;
            v[t] = (j < 800) ? u[j] * inv : d_h1[(size_t)n * 32 + (j - 800)];
        }
        out[j2] = __floats2half2_rn(v[0], v[1]);
    }
}

#define APITCH 72
#define ABUF (128 * APITCH)
#define WBUF (64 * APITCH)

// ---------------- GEMM1 (tensor cores): h1 = elu(U1h @ W1ph + b1) ----------------
// 256 thr (8 warps). Tile M=128 x N=32, K in 3 chunks of 64 (double-buffered).
__global__ void __launch_bounds__(256) k_gemm1t(const float* __restrict__ b1) {
    extern __shared__ __half S[];
    __half* Asm = S;                 // [2][128][72]
    __half* Wsm = S + 2 * ABUF;      // [2][64][72] (only 32 cols used)
    const int tid = threadIdx.x, lane = tid & 31, warp = tid >> 5;
    const int m0 = blockIdx.x * 128;

    const int arow = tid >> 1, ahalf = tid & 1;        // A: 2 thr/row, 32 halfs each
    const int wrow = tid >> 2, wseg = (tid & 3) * 8;   // W: 4 thr/row, 8 halfs each
    const __half* aSrc = &d_U1h[(size_t)(m0 + arow) * 192 + ahalf * 32];
    const __half* wSrc = &d_W1ph[wrow * 32 + wseg];

    float acc[4][4];
#pragma unroll
    for (int i = 0; i < 4; i++)
#pragma unroll
        for (int j = 0; j < 4; j++) acc[i][j] = 0.f;

    // stage chunk 0
    {
        int4 a0 = *(const int4*)(aSrc);
        int4 a1 = *(const int4*)(aSrc + 8);
        int4 a2 = *(const int4*)(aSrc + 16);
        int4 a3 = *(const int4*)(aSrc + 24);
        __half* ad = &Asm[arow * APITCH + ahalf * 32];
        ((int4*)ad)[0] = a0; ((int4*)ad)[1] = a1;
        ((int4*)ad)[2] = a2; ((int4*)ad)[3] = a3;
        int4 w0 = *(const int4*)(wSrc);
        __half* wd = &Wsm[wrow * APITCH + wseg];
        ((int4*)wd)[0] = w0;
    }
    __syncthreads();

    const int aLdRow = lane & 15, aLdColGrp = (lane >> 4) * 8;
    const int bLdRow = (lane & 7) + 8 * ((lane >> 3) & 1), bLdColGrp = (lane >> 4) * 8;

    int buf = 0;
    for (int ch = 0; ch < 3; ch++) {
        int4 pa0, pa1, pa2, pa3, pw0;
        if (ch + 1 < 3) {
            const __half* as = aSrc + (ch + 1) * 64;
            pa0 = *(const int4*)(as);
            pa1 = *(const int4*)(as + 8);
            pa2 = *(const int4*)(as + 16);
            pa3 = *(const int4*)(as + 24);
            pw0 = *(const int4*)(wSrc + (size_t)(ch + 1) * 64 * 32);
        }
        const __half* Ab = &Asm[buf * ABUF];
        const __half* Wb = &Wsm[buf * WBUF];
#pragma unroll
        for (int ks = 0; ks < 4; ks++) {
            uint32_t a[4];
            uint32_t aAddr = (uint32_t)__cvta_generic_to_shared(
                &Ab[(warp * 16 + aLdRow) * APITCH + ks * 16 + aLdColGrp]);
            ldmA4(a, aAddr);
#pragma unroll
            for (int nb = 0; nb < 2; nb++) {
                uint32_t b[4];
                uint32_t bAddr = (uint32_t)__cvta_generic_to_shared(
                    &Wb[(ks * 16 + bLdRow) * APITCH + nb * 16 + bLdColGrp]);
                ldmBT4(b, bAddr);
                mma16816(acc[2 * nb],     a, b[0], b[1]);
                mma16816(acc[2 * nb + 1], a, b[2], b[3]);
            }
        }
        if (ch + 1 < 3) {
            __half* ad = &Asm[(buf ^ 1) * ABUF + arow * APITCH + ahalf * 32];
            ((int4*)ad)[0] = pa0; ((int4*)ad)[1] = pa1;
            ((int4*)ad)[2] = pa2; ((int4*)ad)[3] = pa3;
            __half* wd = &Wsm[(buf ^ 1) * WBUF + wrow * APITCH + wseg];
            ((int4*)wd)[0] = pw0;
        }
        __syncthreads();
        buf ^= 1;
    }

    const int g = lane >> 2, tig = lane & 3;
#pragma unroll
    for (int nb = 0; nb < 2; nb++) {
        int c0 = nb * 16 + tig * 2;
        int c1 = nb * 16 + 8 + tig * 2;
        float2 bv0 = *(const float2*)&b1[c0];
        float2 bv1 = *(const float2*)&b1[c1];
        int rowA = m0 + warp * 16 + g;
        int rowB = rowA + 8;
        float* hA = &d_h1[(size_t)rowA * 32];
        float* hB = &d_h1[(size_t)rowB * 32];
        *(float2*)&hA[c0] = make_float2(eluf(acc[2 * nb][0] + bv0.x), eluf(acc[2 * nb][1] + bv0.y));
        *(float2*)&hB[c0] = make_float2(eluf(acc[2 * nb][2] + bv0.x), eluf(acc[2 * nb][3] + bv0.y));
        *(float2*)&hA[c1] = make_float2(eluf(acc[2 * nb + 1][0] + bv1.x), eluf(acc[2 * nb + 1][1] + bv1.y));
        *(float2*)&hB[c1] = make_float2(eluf(acc[2 * nb + 1][2] + bv1.x), eluf(acc[2 * nb + 1][3] + bv1.y));
    }
}

// ---------------- GEMM2 (tensor cores): h2 = elu(U2h @ W2ph + b2) ----------------
__global__ void __launch_bounds__(256) k_gemm2t(const float* __restrict__ b2) {
    extern __shared__ __half S[];
    __half* Asm = S;                 // [2][128][72]
    __half* Wsm = S + 2 * ABUF;      // [2][64][72]
    const int tid = threadIdx.x, lane = tid & 31, warp = tid >> 5;
    const int m0 = blockIdx.x * 128;

    const int arow = tid >> 1, ahalf = tid & 1;
    const int wrow = tid >> 2, wseg = (tid & 3) * 16;
    const __half* aSrc = &d_U2h[(size_t)(m0 + arow) * 832 + ahalf * 32];
    const __half* wSrc = &d_W2ph[wrow * 64 + wseg];

    float acc[8][4];
#pragma unroll
    for (int i = 0; i < 8; i++)
#pragma unroll
        for (int j = 0; j < 4; j++) acc[i][j] = 0.f;

    {
        int4 a0 = *(const int4*)(aSrc);
        int4 a1 = *(const int4*)(aSrc + 8);
        int4 a2 = *(const int4*)(aSrc + 16);
        int4 a3 = *(const int4*)(aSrc + 24);
        __half* ad = &Asm[arow * APITCH + ahalf * 32];
        ((int4*)ad)[0] = a0; ((int4*)ad)[1] = a1;
        ((int4*)ad)[2] = a2; ((int4*)ad)[3] = a3;
        int4 w0 = *(const int4*)(wSrc);
        int4 w1 = *(const int4*)(wSrc + 8);
        __half* wd = &Wsm[wrow * APITCH + wseg];
        ((int4*)wd)[0] = w0; ((int4*)wd)[1] = w1;
    }
    __syncthreads();

    const int aLdRow = lane & 15, aLdColGrp = (lane >> 4) * 8;
    const int bLdRow = (lane & 7) + 8 * ((lane >> 3) & 1), bLdColGrp = (lane >> 4) * 8;

    int buf = 0;
    for (int ch = 0; ch < 13; ch++) {
        int4 pa0, pa1, pa2, pa3, pw0, pw1;
        if (ch + 1 < 13) {
            const __half* as = aSrc + (ch + 1) * 64;
            pa0 = *(const int4*)(as);
            pa1 = *(const int4*)(as + 8);
            pa2 = *(const int4*)(as + 16);
            pa3 = *(const int4*)(as + 24);
            const __half* ws = wSrc + (size_t)(ch + 1) * 64 * 64;
            pw0 = *(const int4*)(ws);
            pw1 = *(const int4*)(ws + 8);
        }
        const __half* Ab = &Asm[buf * ABUF];
        const __half* Wb = &Wsm[buf * WBUF];
#pragma unroll
        for (int ks = 0; ks < 4; ks++) {
            uint32_t a[4];
            uint32_t aAddr = (uint32_t)__cvta_generic_to_shared(
                &Ab[(warp * 16 + aLdRow) * APITCH + ks * 16 + aLdColGrp]);
            ldmA4(a, aAddr);
#pragma unroll
            for (int nb = 0; nb < 4; nb++) {
                uint32_t b[4];
                uint32_t bAddr = (uint32_t)__cvta_generic_to_shared(
                    &Wb[(ks * 16 + bLdRow) * APITCH + nb * 16 + bLdColGrp]);
                ldmBT4(b, bAddr);
                mma16816(acc[2 * nb],     a, b[0], b[1]);
                mma16816(acc[2 * nb + 1], a, b[2], b[3]);
            }
        }
        if (ch + 1 < 13) {
            __half* ad = &Asm[(buf ^ 1) * ABUF + arow * APITCH + ahalf * 32];
            ((int4*)ad)[0] = pa0; ((int4*)ad)[1] = pa1;
            ((int4*)ad)[2] = pa2; ((int4*)ad)[3] = pa3;
            __half* wd = &Wsm[(buf ^ 1) * WBUF + wrow * APITCH + wseg];
            ((int4*)wd)[0] = pw0; ((int4*)wd)[1] = pw1;
        }
        __syncthreads();
        buf ^= 1;
    }

    const int g = lane >> 2, tig = lane & 3;
#pragma unroll
    for (int nb = 0; nb < 4; nb++) {
        int c0 = nb * 16 + tig * 2;
        int c1 = nb * 16 + 8 + tig * 2;
        float2 bv0 = *(const float2*)&b2[c0];
        float2 bv1 = *(const float2*)&b2[c1];
        int rowA = m0 + warp * 16 + g;
        int rowB = rowA + 8;
        float* hA = &d_h2[(size_t)rowA * 64];
        float* hB = &d_h2[(size_t)rowB * 64];
        *(float2*)&hA[c0] = make_float2(eluf(acc[2 * nb][0] + bv0.x), eluf(acc[2 * nb][1] + bv0.y));
        *(float2*)&hB[c0] = make_float2(eluf(acc[2 * nb][2] + bv0.x), eluf(acc[2 * nb][3] + bv0.y));
        *(float2*)&hA[c1] = make_float2(eluf(acc[2 * nb + 1][0] + bv1.x), eluf(acc[2 * nb + 1][1] + bv1.y));
        *(float2*)&hB[c1] = make_float2(eluf(acc[2 * nb + 1][2] + bv1.x), eluf(acc[2 * nb + 1][3] + bv1.y));
    }
}

// ---------------- pooling + FC + log_softmax ----------------
__global__ void k_head(const int* __restrict__ slices, const float* __restrict__ fcw,
                       const float* __restrict__ fcb, float* __restrict__ out) {
    int b = blockIdx.x;
    int s0 = slices[b], s1 = slices[b + 1];
    __shared__ float red[4][64];
    __shared__ float g[64];
    __shared__ float lg[30];
    int tid = threadIdx.x;  // 256
    int o = tid & 63, part = tid >> 6;
    float acc = 0.f;
    for (int n = s0 + part; n < s1; n += 4) acc += d_h2[(size_t)n * 64 + o];
    red[part][o] = acc;
    __syncthreads();
    if (part == 0) {
        float s = red[0][o] + red[1][o] + red[2][o] + red[3][o];
        g[o] = s / fmaxf((float)(s1 - s0), 1.f);
    }
    __syncthreads();
    if (tid < 30) {
        float l = fcb[tid];
        for (int i = 0; i < 64; i++) l += g[i] * fcw[i * 30 + tid];
        lg[tid] = l;
    }
    __syncthreads();
    if (tid < 30) {
        float m = -1e30f;
        for (int j = 0; j < 30; j++) m = fmaxf(m, lg[j]);
        float se = 0.f;
        for (int j = 0; j < 30; j++) se += expf(lg[j] - m);
        out[b * 30 + tid] = lg[tid] - m - logf(se);
    }
}

// ---------------- launch ----------------
extern "C" void kernel_launch(void* const* d_in, const int* in_sizes, int n_in,
                              void* d_out, int out_size) {
    const float* x      = (const float*)d_in[0];
    const int*   eidx   = (const int*)d_in[1];
    const float* pseudo = (const float*)d_in[2];
    const int*   slices = (const int*)d_in[3];
    const float* W1     = (const float*)d_in[4];
    const float* root1  = (const float*)d_in[5];
    const float* b1     = (const float*)d_in[6];
    const float* W2     = (const float*)d_in[7];
    const float* root2  = (const float*)d_in[8];
    const float* b2     = (const float*)d_in[9];
    const float* fcw    = (const float*)d_in[10];
    const float* fcb    = (const float*)d_in[11];
    float* out = (float*)d_out;

    const int* src = eidx;
    const int* dst = eidx + Ee;

    const int G_SMEM = (2 * ABUF + 2 * WBUF) * 2;  // 55296 B
    cudaFuncSetAttribute(k_gemm1t, cudaFuncAttributeMaxDynamicSharedMemorySize, G_SMEM);
    cudaFuncSetAttribute(k_gemm2t, cudaFuncAttributeMaxDynamicSharedMemorySize, G_SMEM);

    k_init<<<(832 * 64 + 255) / 256, 256>>>(W1, root1, W2, root2);
    k_hist<<<(Ee + 1023) / 1024, 1024>>>(dst);
    k_scan<<<1, 1024>>>();
    k_scatter<<<(Ee + 1023) / 1024, 1024>>>(src, dst, pseudo);
    k_u1<<<Nn / 8, 256>>>(x);
    k_gemm1t<<<Nn / 128, 256, G_SMEM>>>(b1);
    k_u2<<<Nn / 8, 256>>>();
    k_gemm2t<<<Nn / 128, 256, G_SMEM>>>(b2);
    k_head<<<Bb, 256>>>(slices, fcw, fcb, out);
}

// round 9
// speedup vs baseline: 2.0190x; 1.0223x over previous
#include <cuda_runtime.h>
#include <cuda_fp16.h>
#include <math.h>
#include <stdint.h>

#define Nn 51200
#define Ee 819200
#define Bb 64

typedef unsigned long long ull;

// ---------------- scratch (__device__ globals; allocation-free) ----------------
struct __align__(32) EdgeRec { float4 basis; int src; int widx; int p0; int p1; };

__device__ int     d_cnt[Nn];
__device__ int     d_cur[Nn];
__device__ int     d_off[Nn + 1];
__device__ EdgeRec d_edge[Ee];
__device__ __half  d_W1ph[192 * 32];         // fp16 W1 (rows 0..174 = W1, 175..181 = root1, rest 0)
__device__ __half  d_W2ph[832 * 64];         // fp16 W2 (rows 0..799 = W2, 800..831 = root2)
__device__ __half  d_U1h[(size_t)Nn * 192];
__device__ __half  d_h1h[(size_t)Nn * 32];
__device__ __half  d_U2h[(size_t)Nn * 832];
__device__ float   d_gsum[Bb * 64];

__device__ __forceinline__ float eluf(float v) { return v > 0.f ? v : (expf(v) - 1.f); }

// ---------------- mma helpers ----------------
__device__ __forceinline__ void ldmA4(uint32_t* a, uint32_t addr) {
    asm volatile("ldmatrix.sync.aligned.m8n8.x4.shared.b16 {%0,%1,%2,%3}, [%4];"
                 : "=r"(a[0]), "=r"(a[1]), "=r"(a[2]), "=r"(a[3]) : "r"(addr));
}
__device__ __forceinline__ void ldmBT4(uint32_t* b, uint32_t addr) {
    asm volatile("ldmatrix.sync.aligned.m8n8.x4.trans.shared.b16 {%0,%1,%2,%3}, [%4];"
                 : "=r"(b[0]), "=r"(b[1]), "=r"(b[2]), "=r"(b[3]) : "r"(addr));
}
__device__ __forceinline__ void mma16816(float* c, const uint32_t* a, uint32_t b0, uint32_t b1) {
    asm volatile(
        "mma.sync.aligned.m16n8k16.row.col.f32.f16.f16.f32 "
        "{%0,%1,%2,%3}, {%4,%5,%6,%7}, {%8,%9}, {%0,%1,%2,%3};"
        : "+f"(c[0]), "+f"(c[1]), "+f"(c[2]), "+f"(c[3])
        : "r"(a[0]), "r"(a[1]), "r"(a[2]), "r"(a[3]), "r"(b0), "r"(b1));
}

// ---------------- init: zero counters + gsum, quantize weights ----------------
__global__ void k_init(const float* __restrict__ W1, const float* __restrict__ root1,
                       const float* __restrict__ W2, const float* __restrict__ root2) {
    int j = blockIdx.x * blockDim.x + threadIdx.x;
    if (j < Nn) { d_cnt[j] = 0; d_cur[j] = 0; }
    if (j < Bb * 64) d_gsum[j] = 0.f;
    if (j < 192 * 32) {
        float v = 0.f;
        if (j < 5600) v = W1[j];
        else if (j < 5824) v = root1[j - 5600];
        d_W1ph[j] = __float2half_rn(v);
    }
    if (j < 832 * 64) {
        float v;
        if (j < 51200) v = W2[j];
        else v = root2[j - 51200];
        d_W2ph[j] = __float2half_rn(v);
    }
}

__global__ void k_hist(const int* __restrict__ dst) {
    int e = blockIdx.x * blockDim.x + threadIdx.x;
    if (e < Ee) atomicAdd(&d_cnt[dst[e]], 1);
}

__global__ void k_scan() {
    __shared__ int s[1024];
    int t = threadIdx.x;
    const int CH = (Nn + 1023) / 1024;  // 50
    int base = t * CH;
    int sum = 0;
    for (int j = 0; j < CH; j++) {
        int idx = base + j;
        if (idx < Nn) sum += d_cnt[idx];
    }
    s[t] = sum;
    __syncthreads();
    for (int ofs = 1; ofs < 1024; ofs <<= 1) {
        int v = (t >= ofs) ? s[t - ofs] : 0;
        __syncthreads();
        if (t >= ofs) s[t] += v;
        __syncthreads();
    }
    int run = (t == 0) ? 0 : s[t - 1];
    for (int j = 0; j < CH; j++) {
        int idx = base + j;
        if (idx < Nn) { d_off[idx] = run; run += d_cnt[idx]; }
    }
    if (t == 1023) d_off[Nn] = run;
}

__global__ void k_scatter(const int* __restrict__ src, const int* __restrict__ dst,
                          const float* __restrict__ pseudo) {
    int e = blockIdx.x * blockDim.x + threadIdx.x;
    if (e >= Ee) return;
    int d = dst[e];
    int pos = d_off[d] + atomicAdd(&d_cur[d], 1);
    float v0 = pseudo[2 * e] * 4.f;
    float v1 = pseudo[2 * e + 1] * 4.f;
    int lo0 = __float2int_rd(v0); lo0 = lo0 < 0 ? 0 : (lo0 > 3 ? 3 : lo0);
    int lo1 = __float2int_rd(v1); lo1 = lo1 < 0 ? 0 : (lo1 > 3 ? 3 : lo1);
    float f0 = v0 - (float)lo0, f1 = v1 - (float)lo1;
    float g0 = 1.f - f0, g1 = 1.f - f1;
    int k0 = lo0 * 5 + lo1;
    int wx = k0 | ((k0 + 1) << 8) | ((k0 + 5) << 16) | ((k0 + 6) << 24);
    *(float4*)&d_edge[pos].basis = make_float4(g0 * g1, g0 * f1, f0 * g1, f0 * f1);
    *(int4*)&d_edge[pos].src = make_int4(src[e], wx, 0, 0);
}

// ---------------- U1 build (fp16 output) ----------------
__global__ void k_u1(const float* __restrict__ x) {
    __shared__ float su[8][4][176];
    int tid = threadIdx.x;
    int warp = tid >> 5, lane = tid & 31;
    int n = blockIdx.x * 8 + warp;
    if (n >= Nn) return;
    float(*u)[176] = su[warp];
    for (int j = lane; j < 4 * 176; j += 32) ((float*)u)[j] = 0.f;
    __syncwarp();
    int beg = d_off[n], end = d_off[n + 1];
    int eb = lane / 7, i = lane - eb * 7;
    if (lane < 28) {
        for (int p0 = beg; p0 < end; p0 += 4) {
            int p = p0 + eb;
            if (p < end) {
                float4 bs = *(const float4*)&d_edge[p].basis;
                int2 sw = *(const int2*)&d_edge[p].src;
                int sv = sw.x, wx = sw.y;
                float xv = x[sv * 7 + i];
                u[eb][(wx & 255) * 7 + i]         += bs.x * xv;
                u[eb][((wx >> 8) & 255) * 7 + i]  += bs.y * xv;
                u[eb][((wx >> 16) & 255) * 7 + i] += bs.z * xv;
                u[eb][((wx >> 24) & 255) * 7 + i] += bs.w * xv;
            }
        }
    }
    __syncwarp();
    float inv = 1.f / fmaxf((float)(end - beg), 1.f);
    __half2* out = (__half2*)&d_U1h[(size_t)n * 192];
    for (int j2 = lane; j2 < 96; j2 += 32) {
        float v[2];
#pragma unroll
        for (int t = 0; t < 2; t++) {
            int j = 2 * j2 + t;
            if (j < 175)      v[t] = (u[0][j] + u[1][j] + u[2][j] + u[3][j]) * inv;
            else if (j < 182) v[t] = x[n * 7 + (j - 175)];
            else              v[t] = 0.f;
        }
        out[j2] = __floats2half2_rn(v[0], v[1]);
    }
}

// ---------------- U2 build (reads fp16 h1, fp16 output, 2-edge prefetch) ----------------
__global__ void k_u2() {
    __shared__ float su[8][800];
    int tid = threadIdx.x;
    int warp = tid >> 5, lane = tid & 31;
    int n = blockIdx.x * 8 + warp;
    if (n >= Nn) return;
    float* u = su[warp];
    for (int j = lane; j < 800; j += 32) u[j] = 0.f;
    __syncwarp();
    int beg = d_off[n], end = d_off[n + 1];
    float4 bs0, bs1; int wx0 = 0, wx1 = 0; float hv0 = 0.f, hv1 = 0.f;
    if (beg < end) {
        bs0 = *(const float4*)&d_edge[beg].basis;
        int2 sw = *(const int2*)&d_edge[beg].src;
        wx0 = sw.y;
        hv0 = __half2float(d_h1h[(size_t)sw.x * 32 + lane]);
    }
    if (beg + 1 < end) {
        bs1 = *(const float4*)&d_edge[beg + 1].basis;
        int2 sw = *(const int2*)&d_edge[beg + 1].src;
        wx1 = sw.y;
        hv1 = __half2float(d_h1h[(size_t)sw.x * 32 + lane]);
    }
    for (int p = beg; p < end; p++) {
        float4 bs_n; int wx_n = 0; float hv_n = 0.f;
        if (p + 2 < end) {
            bs_n = *(const float4*)&d_edge[p + 2].basis;
            int2 sw = *(const int2*)&d_edge[p + 2].src;
            wx_n = sw.y;
            hv_n = __half2float(d_h1h[(size_t)sw.x * 32 + lane]);
        }
        u[(wx0 & 255) * 32 + lane]         += bs0.x * hv0;
        u[((wx0 >> 8) & 255) * 32 + lane]  += bs0.y * hv0;
        u[((wx0 >> 16) & 255) * 32 + lane] += bs0.z * hv0;
        u[((wx0 >> 24) & 255) * 32 + lane] += bs0.w * hv0;
        bs0 = bs1; wx0 = wx1; hv0 = hv1;
        bs1 = bs_n; wx1 = wx_n; hv1 = hv_n;
    }
    __syncwarp();
    float inv = 1.f / fmaxf((float)(end - beg), 1.f);
    __half2* out = (__half2*)&d_U2h[(size_t)n * 832];
    for (int j2 = lane; j2 < 416; j2 += 32) {
        float v[2];
#pragma unroll
        for (int t = 0; t < 2; t++) {
            int j = 2 * j2 + t;
            v[t] = (j < 800) ? u[j] * inv
                             : __half2float(d_h1h[(size_t)n * 32 + (j - 800)]);
        }
        out[j2] = __floats2half2_rn(v[0], v[1]);
    }
}

#define APITCH 72
#define ABUF (128 * APITCH)
#define WBUF (64 * APITCH)

// ---------------- GEMM1 (tensor cores): h1 = elu(U1h @ W1ph + b1), fp16 out ----------------
__global__ void __launch_bounds__(256) k_gemm1t(const float* __restrict__ b1) {
    extern __shared__ __half S[];
    __half* Asm = S;                 // [2][128][72]
    __half* Wsm = S + 2 * ABUF;      // [2][64][72] (only 32 cols used)
    const int tid = threadIdx.x, lane = tid & 31, warp = tid >> 5;
    const int m0 = blockIdx.x * 128;

    const int arow = tid >> 1, ahalf = tid & 1;
    const int wrow = tid >> 2, wseg = (tid & 3) * 8;
    const __half* aSrc = &d_U1h[(size_t)(m0 + arow) * 192 + ahalf * 32];
    const __half* wSrc = &d_W1ph[wrow * 32 + wseg];

    float acc[4][4];
#pragma unroll
    for (int i = 0; i < 4; i++)
#pragma unroll
        for (int j = 0; j < 4; j++) acc[i][j] = 0.f;

    {
        int4 a0 = *(const int4*)(aSrc);
        int4 a1 = *(const int4*)(aSrc + 8);
        int4 a2 = *(const int4*)(aSrc + 16);
        int4 a3 = *(const int4*)(aSrc + 24);
        __half* ad = &Asm[arow * APITCH + ahalf * 32];
        ((int4*)ad)[0] = a0; ((int4*)ad)[1] = a1;
        ((int4*)ad)[2] = a2; ((int4*)ad)[3] = a3;
        int4 w0 = *(const int4*)(wSrc);
        __half* wd = &Wsm[wrow * APITCH + wseg];
        ((int4*)wd)[0] = w0;
    }
    __syncthreads();

    const int aLdRow = lane & 15, aLdColGrp = (lane >> 4) * 8;
    const int bLdRow = (lane & 7) + 8 * ((lane >> 3) & 1), bLdColGrp = (lane >> 4) * 8;

    int buf = 0;
    for (int ch = 0; ch < 3; ch++) {
        int4 pa0, pa1, pa2, pa3, pw0;
        if (ch + 1 < 3) {
            const __half* as = aSrc + (ch + 1) * 64;
            pa0 = *(const int4*)(as);
            pa1 = *(const int4*)(as + 8);
            pa2 = *(const int4*)(as + 16);
            pa3 = *(const int4*)(as + 24);
            pw0 = *(const int4*)(wSrc + (size_t)(ch + 1) * 64 * 32);
        }
        const __half* Ab = &Asm[buf * ABUF];
        const __half* Wb = &Wsm[buf * WBUF];
#pragma unroll
        for (int ks = 0; ks < 4; ks++) {
            uint32_t a[4];
            uint32_t aAddr = (uint32_t)__cvta_generic_to_shared(
                &Ab[(warp * 16 + aLdRow) * APITCH + ks * 16 + aLdColGrp]);
            ldmA4(a, aAddr);
#pragma unroll
            for (int nb = 0; nb < 2; nb++) {
                uint32_t b[4];
                uint32_t bAddr = (uint32_t)__cvta_generic_to_shared(
                    &Wb[(ks * 16 + bLdRow) * APITCH + nb * 16 + bLdColGrp]);
                ldmBT4(b, bAddr);
                mma16816(acc[2 * nb],     a, b[0], b[1]);
                mma16816(acc[2 * nb + 1], a, b[2], b[3]);
            }
        }
        if (ch + 1 < 3) {
            __half* ad = &Asm[(buf ^ 1) * ABUF + arow * APITCH + ahalf * 32];
            ((int4*)ad)[0] = pa0; ((int4*)ad)[1] = pa1;
            ((int4*)ad)[2] = pa2; ((int4*)ad)[3] = pa3;
            __half* wd = &Wsm[(buf ^ 1) * WBUF + wrow * APITCH + wseg];
            ((int4*)wd)[0] = pw0;
        }
        __syncthreads();
        buf ^= 1;
    }

    const int g = lane >> 2, tig = lane & 3;
#pragma unroll
    for (int nb = 0; nb < 2; nb++) {
        int c0 = nb * 16 + tig * 2;
        int c1 = nb * 16 + 8 + tig * 2;
        float2 bv0 = *(const float2*)&b1[c0];
        float2 bv1 = *(const float2*)&b1[c1];
        int rowA = m0 + warp * 16 + g;
        int rowB = rowA + 8;
        __half* hA = &d_h1h[(size_t)rowA * 32];
        __half* hB = &d_h1h[(size_t)rowB * 32];
        *(__half2*)&hA[c0] = __floats2half2_rn(eluf(acc[2 * nb][0] + bv0.x), eluf(acc[2 * nb][1] + bv0.y));
        *(__half2*)&hB[c0] = __floats2half2_rn(eluf(acc[2 * nb][2] + bv0.x), eluf(acc[2 * nb][3] + bv0.y));
        *(__half2*)&hA[c1] = __floats2half2_rn(eluf(acc[2 * nb + 1][0] + bv1.x), eluf(acc[2 * nb + 1][1] + bv1.y));
        *(__half2*)&hB[c1] = __floats2half2_rn(eluf(acc[2 * nb + 1][2] + bv1.x), eluf(acc[2 * nb + 1][3] + bv1.y));
    }
}

// ---------------- GEMM2 (tensor cores) + fused mean-pool ----------------
// elu(U2h @ W2ph + b2) summed per graph directly into d_gsum (no h2 array).
// 800 % 16 == 0 -> each warp's 16 rows belong to exactly one graph.
__global__ void __launch_bounds__(256) k_gemm2t(const float* __restrict__ b2) {
    extern __shared__ __half S[];
    __half* Asm = S;                 // [2][128][72]
    __half* Wsm = S + 2 * ABUF;      // [2][64][72]
    const int tid = threadIdx.x, lane = tid & 31, warp = tid >> 5;
    const int m0 = blockIdx.x * 128;

    const int arow = tid >> 1, ahalf = tid & 1;
    const int wrow = tid >> 2, wseg = (tid & 3) * 16;
    const __half* aSrc = &d_U2h[(size_t)(m0 + arow) * 832 + ahalf * 32];
    const __half* wSrc = &d_W2ph[wrow * 64 + wseg];

    float acc[8][4];
#pragma unroll
    for (int i = 0; i < 8; i++)
#pragma unroll
        for (int j = 0; j < 4; j++) acc[i][j] = 0.f;

    {
        int4 a0 = *(const int4*)(aSrc);
        int4 a1 = *(const int4*)(aSrc + 8);
        int4 a2 = *(const int4*)(aSrc + 16);
        int4 a3 = *(const int4*)(aSrc + 24);
        __half* ad = &Asm[arow * APITCH + ahalf * 32];
        ((int4*)ad)[0] = a0; ((int4*)ad)[1] = a1;
        ((int4*)ad)[2] = a2; ((int4*)ad)[3] = a3;
        int4 w0 = *(const int4*)(wSrc);
        int4 w1 = *(const int4*)(wSrc + 8);
        __half* wd = &Wsm[wrow * APITCH + wseg];
        ((int4*)wd)[0] = w0; ((int4*)wd)[1] = w1;
    }
    __syncthreads();

    const int aLdRow = lane & 15, aLdColGrp = (lane >> 4) * 8;
    const int bLdRow = (lane & 7) + 8 * ((lane >> 3) & 1), bLdColGrp = (lane >> 4) * 8;

    int buf = 0;
    for (int ch = 0; ch < 13; ch++) {
        int4 pa0, pa1, pa2, pa3, pw0, pw1;
        if (ch + 1 < 13) {
            const __half* as = aSrc + (ch + 1) * 64;
            pa0 = *(const int4*)(as);
            pa1 = *(const int4*)(as + 8);
            pa2 = *(const int4*)(as + 16);
            pa3 = *(const int4*)(as + 24);
            const __half* ws = wSrc + (size_t)(ch + 1) * 64 * 64;
            pw0 = *(const int4*)(ws);
            pw1 = *(const int4*)(ws + 8);
        }
        const __half* Ab = &Asm[buf * ABUF];
        const __half* Wb = &Wsm[buf * WBUF];
#pragma unroll
        for (int ks = 0; ks < 4; ks++) {
            uint32_t a[4];
            uint32_t aAddr = (uint32_t)__cvta_generic_to_shared(
                &Ab[(warp * 16 + aLdRow) * APITCH + ks * 16 + aLdColGrp]);
            ldmA4(a, aAddr);
#pragma unroll
            for (int nb = 0; nb < 4; nb++) {
                uint32_t b[4];
                uint32_t bAddr = (uint32_t)__cvta_generic_to_shared(
                    &Wb[(ks * 16 + bLdRow) * APITCH + nb * 16 + bLdColGrp]);
                ldmBT4(b, bAddr);
                mma16816(acc[2 * nb],     a, b[0], b[1]);
                mma16816(acc[2 * nb + 1], a, b[2], b[3]);
            }
        }
        if (ch + 1 < 13) {
            __half* ad = &Asm[(buf ^ 1) * ABUF + arow * APITCH + ahalf * 32];
            ((int4*)ad)[0] = pa0; ((int4*)ad)[1] = pa1;
            ((int4*)ad)[2] = pa2; ((int4*)ad)[3] = pa3;
            __half* wd = &Wsm[(buf ^ 1) * WBUF + wrow * APITCH + wseg];
            ((int4*)wd)[0] = pw0; ((int4*)wd)[1] = pw1;
        }
        __syncthreads();
        buf ^= 1;
    }

    // fused epilogue: elu + per-warp row-sum + atomic into graph accumulator
    const int tig = lane & 3;
    const int gg = (m0 + warp * 16) / 800;     // graph id (uniform per warp)
    float s[16];
#pragma unroll
    for (int nb = 0; nb < 4; nb++) {
        float2 bv0 = *(const float2*)&b2[nb * 16 + tig * 2];
        float2 bv1 = *(const float2*)&b2[nb * 16 + 8 + tig * 2];
        s[nb * 4 + 0] = eluf(acc[2 * nb][0] + bv0.x) + eluf(acc[2 * nb][2] + bv0.x);
        s[nb * 4 + 1] = eluf(acc[2 * nb][1] + bv0.y) + eluf(acc[2 * nb][3] + bv0.y);
        s[nb * 4 + 2] = eluf(acc[2 * nb + 1][0] + bv1.x) + eluf(acc[2 * nb + 1][2] + bv1.x);
        s[nb * 4 + 3] = eluf(acc[2 * nb + 1][1] + bv1.y) + eluf(acc[2 * nb + 1][3] + bv1.y);
    }
#pragma unroll
    for (int ofs = 4; ofs < 32; ofs <<= 1)
#pragma unroll
        for (int i = 0; i < 16; i++)
            s[i] += __shfl_xor_sync(0xffffffffu, s[i], ofs, 32);
    if (lane < 4) {
        float* gb = &d_gsum[gg * 64];
#pragma unroll
        for (int nb = 0; nb < 4; nb++) {
            atomicAdd(&gb[nb * 16 + lane * 2],     s[nb * 4 + 0]);
            atomicAdd(&gb[nb * 16 + lane * 2 + 1], s[nb * 4 + 1]);
            atomicAdd(&gb[nb * 16 + 8 + lane * 2],     s[nb * 4 + 2]);
            atomicAdd(&gb[nb * 16 + 8 + lane * 2 + 1], s[nb * 4 + 3]);
        }
    }
}

// ---------------- head: mean + FC + log_softmax from d_gsum ----------------
__global__ void k_head(const int* __restrict__ slices, const float* __restrict__ fcw,
                       const float* __restrict__ fcb, float* __restrict__ out) {
    int b = blockIdx.x;
    int tid = threadIdx.x;  // 32
    __shared__ float g[64];
    __shared__ float lg[30];
    float cnt = fmaxf((float)(slices[b + 1] - slices[b]), 1.f);
    for (int i = tid; i < 64; i += 32) g[i] = d_gsum[b * 64 + i] / cnt;
    __syncwarp();
    if (tid < 30) {
        float l = fcb[tid];
        for (int i = 0; i < 64; i++) l += g[i] * fcw[i * 30 + tid];
        lg[tid] = l;
    }
    __syncwarp();
    if (tid < 30) {
        float m = -1e30f;
        for (int j = 0; j < 30; j++) m = fmaxf(m, lg[j]);
        float se = 0.f;
        for (int j = 0; j < 30; j++) se += expf(lg[j] - m);
        out[b * 30 + tid] = lg[tid] - m - logf(se);
    }
}

// ---------------- launch ----------------
extern "C" void kernel_launch(void* const* d_in, const int* in_sizes, int n_in,
                              void* d_out, int out_size) {
    const float* x      = (const float*)d_in[0];
    const int*   eidx   = (const int*)d_in[1];
    const float* pseudo = (const float*)d_in[2];
    const int*   slices = (const int*)d_in[3];
    const float* W1     = (const float*)d_in[4];
    const float* root1  = (const float*)d_in[5];
    const float* b1     = (const float*)d_in[6];
    const float* W2     = (const float*)d_in[7];
    const float* root2  = (const float*)d_in[8];
    const float* b2     = (const float*)d_in[9];
    const float* fcw    = (const float*)d_in[10];
    const float* fcb    = (const float*)d_in[11];
    float* out = (float*)d_out;

    const int* src = eidx;
    const int* dst = eidx + Ee;

    const int G_SMEM = (2 * ABUF + 2 * WBUF) * 2;  // 55296 B
    cudaFuncSetAttribute(k_gemm1t, cudaFuncAttributeMaxDynamicSharedMemorySize, G_SMEM);
    cudaFuncSetAttribute(k_gemm2t, cudaFuncAttributeMaxDynamicSharedMemorySize, G_SMEM);

    k_init<<<(832 * 64 + 255) / 256, 256>>>(W1, root1, W2, root2);
    k_hist<<<(Ee + 1023) / 1024, 1024>>>(dst);
    k_scan<<<1, 1024>>>();
    k_scatter<<<(Ee + 1023) / 1024, 1024>>>(src, dst, pseudo);
    k_u1<<<Nn / 8, 256>>>(x);
    k_gemm1t<<<Nn / 128, 256, G_SMEM>>>(b1);
    k_u2<<<Nn / 8, 256>>>();
    k_gemm2t<<<Nn / 128, 256, G_SMEM>>>(b2);
    k_head<<<Bb, 32>>>(slices, fcw, fcb, out);
}

// round 10
// speedup vs baseline: 2.0558x; 1.0183x over previous
#include <cuda_runtime.h>
#include <cuda_fp16.h>
#include <math.h>
#include <stdint.h>

#define Nn 51200
#define Ee 819200
#define Bb 64

typedef unsigned long long ull;

// ---------------- scratch (__device__ globals; allocation-free) ----------------
struct __align__(16) Edge16 { int src; int widx; unsigned b01; unsigned b23; };

__device__ int     d_cnt[Nn];
__device__ int     d_cur[Nn];
__device__ int     d_off[Nn + 1];
__device__ Edge16  d_edge[Ee];
__device__ __half  d_W1ph[192 * 32];         // fp16 W1 (rows 0..174 = W1, 175..181 = root1, rest 0)
__device__ __half  d_W2ph[832 * 64];         // fp16 W2 (rows 0..799 = W2, 800..831 = root2)
__device__ __half  d_U1h[(size_t)Nn * 192];
__device__ __half  d_h1h[(size_t)Nn * 32];
__device__ __half  d_U2h[(size_t)Nn * 832];
__device__ float   d_gsum[Bb * 64];

__device__ __forceinline__ float eluf(float v) { return v > 0.f ? v : (expf(v) - 1.f); }

// ---------------- mma helpers ----------------
__device__ __forceinline__ void ldmA4(uint32_t* a, uint32_t addr) {
    asm volatile("ldmatrix.sync.aligned.m8n8.x4.shared.b16 {%0,%1,%2,%3}, [%4];"
                 : "=r"(a[0]), "=r"(a[1]), "=r"(a[2]), "=r"(a[3]) : "r"(addr));
}
__device__ __forceinline__ void ldmBT4(uint32_t* b, uint32_t addr) {
    asm volatile("ldmatrix.sync.aligned.m8n8.x4.trans.shared.b16 {%0,%1,%2,%3}, [%4];"
                 : "=r"(b[0]), "=r"(b[1]), "=r"(b[2]), "=r"(b[3]) : "r"(addr));
}
__device__ __forceinline__ void mma16816(float* c, const uint32_t* a, uint32_t b0, uint32_t b1) {
    asm volatile(
        "mma.sync.aligned.m16n8k16.row.col.f32.f16.f16.f32 "
        "{%0,%1,%2,%3}, {%4,%5,%6,%7}, {%8,%9}, {%0,%1,%2,%3};"
        : "+f"(c[0]), "+f"(c[1]), "+f"(c[2]), "+f"(c[3])
        : "r"(a[0]), "r"(a[1]), "r"(a[2]), "r"(a[3]), "r"(b0), "r"(b1));
}

__device__ __forceinline__ float2 b2f(unsigned v) {
    __half2 h = *reinterpret_cast<__half2*>(&v);
    return __half22float2(h);
}

// ---------------- init: zero counters + gsum, quantize weights ----------------
__global__ void k_init(const float* __restrict__ W1, const float* __restrict__ root1,
                       const float* __restrict__ W2, const float* __restrict__ root2) {
    int j = blockIdx.x * blockDim.x + threadIdx.x;
    if (j < Nn) { d_cnt[j] = 0; d_cur[j] = 0; }
    if (j < Bb * 64) d_gsum[j] = 0.f;
    if (j < 192 * 32) {
        float v = 0.f;
        if (j < 5600) v = W1[j];
        else if (j < 5824) v = root1[j - 5600];
        d_W1ph[j] = __float2half_rn(v);
    }
    if (j < 832 * 64) {
        float v;
        if (j < 51200) v = W2[j];
        else v = root2[j - 51200];
        d_W2ph[j] = __float2half_rn(v);
    }
}

__global__ void k_hist(const int* __restrict__ dst) {
    int e = blockIdx.x * blockDim.x + threadIdx.x;
    if (e < Ee) atomicAdd(&d_cnt[dst[e]], 1);
}

__global__ void k_scan() {
    __shared__ int s[1024];
    int t = threadIdx.x;
    const int CH = (Nn + 1023) / 1024;  // 50
    int base = t * CH;
    int sum = 0;
    for (int j = 0; j < CH; j++) {
        int idx = base + j;
        if (idx < Nn) sum += d_cnt[idx];
    }
    s[t] = sum;
    __syncthreads();
    for (int ofs = 1; ofs < 1024; ofs <<= 1) {
        int v = (t >= ofs) ? s[t - ofs] : 0;
        __syncthreads();
        if (t >= ofs) s[t] += v;
        __syncthreads();
    }
    int run = (t == 0) ? 0 : s[t - 1];
    for (int j = 0; j < CH; j++) {
        int idx = base + j;
        if (idx < Nn) { d_off[idx] = run; run += d_cnt[idx]; }
    }
    if (t == 1023) d_off[Nn] = run;
}

__global__ void k_scatter(const int* __restrict__ src, const int* __restrict__ dst,
                          const float* __restrict__ pseudo) {
    int e = blockIdx.x * blockDim.x + threadIdx.x;
    if (e >= Ee) return;
    int d = dst[e];
    int pos = d_off[d] + atomicAdd(&d_cur[d], 1);
    float2 ps = *(const float2*)&pseudo[2 * e];
    float v0 = ps.x * 4.f;
    float v1 = ps.y * 4.f;
    int lo0 = __float2int_rd(v0); lo0 = lo0 < 0 ? 0 : (lo0 > 3 ? 3 : lo0);
    int lo1 = __float2int_rd(v1); lo1 = lo1 < 0 ? 0 : (lo1 > 3 ? 3 : lo1);
    float f0 = v0 - (float)lo0, f1 = v1 - (float)lo1;
    float g0 = 1.f - f0, g1 = 1.f - f1;
    int k0 = lo0 * 5 + lo1;
    int wx = k0 | ((k0 + 1) << 8) | ((k0 + 5) << 16) | ((k0 + 6) << 24);
    __half2 h01 = __floats2half2_rn(g0 * g1, g0 * f1);
    __half2 h23 = __floats2half2_rn(f0 * g1, f0 * f1);
    int4 rec;
    rec.x = src[e];
    rec.y = wx;
    rec.z = *reinterpret_cast<int*>(&h01);
    rec.w = *reinterpret_cast<int*>(&h23);
    *(int4*)&d_edge[pos] = rec;
}

// ---------------- U1 build (16B records, fp16 output) ----------------
__global__ void k_u1(const float* __restrict__ x) {
    __shared__ float su[8][4][176];
    int tid = threadIdx.x;
    int warp = tid >> 5, lane = tid & 31;
    int n = blockIdx.x * 8 + warp;
    if (n >= Nn) return;
    float(*u)[176] = su[warp];
    for (int j = lane; j < 4 * 176; j += 32) ((float*)u)[j] = 0.f;
    __syncwarp();
    int beg = d_off[n], end = d_off[n + 1];
    int eb = lane / 7, i = lane - eb * 7;
    if (lane < 28) {
        for (int p0 = beg; p0 < end; p0 += 4) {
            int p = p0 + eb;
            if (p < end) {
                int4 rec = *(const int4*)&d_edge[p];
                float2 b01 = b2f(rec.z), b23 = b2f(rec.w);
                int wx = rec.y;
                float xv = x[rec.x * 7 + i];
                u[eb][(wx & 255) * 7 + i]         += b01.x * xv;
                u[eb][((wx >> 8) & 255) * 7 + i]  += b01.y * xv;
                u[eb][((wx >> 16) & 255) * 7 + i] += b23.x * xv;
                u[eb][((wx >> 24) & 255) * 7 + i] += b23.y * xv;
            }
        }
    }
    __syncwarp();
    float inv = 1.f / fmaxf((float)(end - beg), 1.f);
    __half2* out = (__half2*)&d_U1h[(size_t)n * 192];
    for (int j2 = lane; j2 < 96; j2 += 32) {
        float v[2];
#pragma unroll
        for (int t = 0; t < 2; t++) {
            int j = 2 * j2 + t;
            if (j < 175)      v[t] = (u[0][j] + u[1][j] + u[2][j] + u[3][j]) * inv;
            else if (j < 182) v[t] = x[n * 7 + (j - 175)];
            else              v[t] = 0.f;
        }
        out[j2] = __floats2half2_rn(v[0], v[1]);
    }
}

// ---------------- U2 build: 2 warps/node, 16B records, prefetch-2 ----------------
// block 256 thr = 8 warps = 4 nodes x 2 warps. Each warp owns one 800-float bank
// and accumulates its stride-2 half of the edge list; banks summed at writeout.
__global__ void k_u2() {
    __shared__ float su[4][2][800];
    int tid = threadIdx.x;
    int warp = tid >> 5, lane = tid & 31;
    int node = warp >> 1, half = warp & 1;
    int n = blockIdx.x * 4 + node;
    float* u = su[node][half];
    for (int j = lane; j < 800; j += 32) u[j] = 0.f;
    int beg = d_off[n], end = d_off[n + 1];
    int p = beg + half;
    // prefetch two edges of this warp's stride-2 chain
    int4 r0 = make_int4(0, 0, 0, 0), r1 = make_int4(0, 0, 0, 0);
    float hv0 = 0.f, hv1 = 0.f;
    if (p < end) {
        r0 = *(const int4*)&d_edge[p];
        hv0 = __half2float(d_h1h[(size_t)r0.x * 32 + lane]);
    }
    if (p + 2 < end) {
        r1 = *(const int4*)&d_edge[p + 2];
        hv1 = __half2float(d_h1h[(size_t)r1.x * 32 + lane]);
    }
    for (; p < end; p += 2) {
        int4 rn = make_int4(0, 0, 0, 0); float hvn = 0.f;
        if (p + 4 < end) {
            rn = *(const int4*)&d_edge[p + 4];
            hvn = __half2float(d_h1h[(size_t)rn.x * 32 + lane]);
        }
        float2 b01 = b2f(r0.z), b23 = b2f(r0.w);
        int wx = r0.y;
        u[(wx & 255) * 32 + lane]         += b01.x * hv0;
        u[((wx >> 8) & 255) * 32 + lane]  += b01.y * hv0;
        u[((wx >> 16) & 255) * 32 + lane] += b23.x * hv0;
        u[((wx >> 24) & 255) * 32 + lane] += b23.y * hv0;
        r0 = r1; hv0 = hv1;
        r1 = rn; hv1 = hvn;
    }
    __syncthreads();
    // merge banks + tail; the two warps of a pair split the 416 half2 outputs
    float inv = 1.f / fmaxf((float)(end - beg), 1.f);
    __half2* out = (__half2*)&d_U2h[(size_t)n * 832];
    const float* u0 = su[node][0];
    const float* u1 = su[node][1];
    for (int j2 = half * 208 + lane; j2 < half * 208 + 208; j2 += 32) {
        float v[2];
#pragma unroll
        for (int t = 0; t < 2; t++) {
            int j = 2 * j2 + t;
            v[t] = (j < 800) ? (u0[j] + u1[j]) * inv
                             : __half2float(d_h1h[(size_t)n * 32 + (j - 800)]);
        }
        out[j2] = __floats2half2_rn(v[0], v[1]);
    }
}

#define APITCH 72
#define ABUF (128 * APITCH)
#define WBUF (64 * APITCH)

// ---------------- GEMM1 (tensor cores): h1 = elu(U1h @ W1ph + b1), fp16 out ----------------
__global__ void __launch_bounds__(256) k_gemm1t(const float* __restrict__ b1) {
    extern __shared__ __half S[];
    __half* Asm = S;                 // [2][128][72]
    __half* Wsm = S + 2 * ABUF;      // [2][64][72] (only 32 cols used)
    const int tid = threadIdx.x, lane = tid & 31, warp = tid >> 5;
    const int m0 = blockIdx.x * 128;

    const int arow = tid >> 1, ahalf = tid & 1;
    const int wrow = tid >> 2, wseg = (tid & 3) * 8;
    const __half* aSrc = &d_U1h[(size_t)(m0 + arow) * 192 + ahalf * 32];
    const __half* wSrc = &d_W1ph[wrow * 32 + wseg];

    float acc[4][4];
#pragma unroll
    for (int i = 0; i < 4; i++)
#pragma unroll
        for (int j = 0; j < 4; j++) acc[i][j] = 0.f;

    {
        int4 a0 = *(const int4*)(aSrc);
        int4 a1 = *(const int4*)(aSrc + 8);
        int4 a2 = *(const int4*)(aSrc + 16);
        int4 a3 = *(const int4*)(aSrc + 24);
        __half* ad = &Asm[arow * APITCH + ahalf * 32];
        ((int4*)ad)[0] = a0; ((int4*)ad)[1] = a1;
        ((int4*)ad)[2] = a2; ((int4*)ad)[3] = a3;
        int4 w0 = *(const int4*)(wSrc);
        __half* wd = &Wsm[wrow * APITCH + wseg];
        ((int4*)wd)[0] = w0;
    }
    __syncthreads();

    const int aLdRow = lane & 15, aLdColGrp = (lane >> 4) * 8;
    const int bLdRow = (lane & 7) + 8 * ((lane >> 3) & 1), bLdColGrp = (lane >> 4) * 8;

    int buf = 0;
    for (int ch = 0; ch < 3; ch++) {
        int4 pa0, pa1, pa2, pa3, pw0;
        if (ch + 1 < 3) {
            const __half* as = aSrc + (ch + 1) * 64;
            pa0 = *(const int4*)(as);
            pa1 = *(const int4*)(as + 8);
            pa2 = *(const int4*)(as + 16);
            pa3 = *(const int4*)(as + 24);
            pw0 = *(const int4*)(wSrc + (size_t)(ch + 1) * 64 * 32);
        }
        const __half* Ab = &Asm[buf * ABUF];
        const __half* Wb = &Wsm[buf * WBUF];
#pragma unroll
        for (int ks = 0; ks < 4; ks++) {
            uint32_t a[4];
            uint32_t aAddr = (uint32_t)__cvta_generic_to_shared(
                &Ab[(warp * 16 + aLdRow) * APITCH + ks * 16 + aLdColGrp]);
            ldmA4(a, aAddr);
#pragma unroll
            for (int nb = 0; nb < 2; nb++) {
                uint32_t b[4];
                uint32_t bAddr = (uint32_t)__cvta_generic_to_shared(
                    &Wb[(ks * 16 + bLdRow) * APITCH + nb * 16 + bLdColGrp]);
                ldmBT4(b, bAddr);
                mma16816(acc[2 * nb],     a, b[0], b[1]);
                mma16816(acc[2 * nb + 1], a, b[2], b[3]);
            }
        }
        if (ch + 1 < 3) {
            __half* ad = &Asm[(buf ^ 1) * ABUF + arow * APITCH + ahalf * 32];
            ((int4*)ad)[0] = pa0; ((int4*)ad)[1] = pa1;
            ((int4*)ad)[2] = pa2; ((int4*)ad)[3] = pa3;
            __half* wd = &Wsm[(buf ^ 1) * WBUF + wrow * APITCH + wseg];
            ((int4*)wd)[0] = pw0;
        }
        __syncthreads();
        buf ^= 1;
    }

    const int g = lane >> 2, tig = lane & 3;
#pragma unroll
    for (int nb = 0; nb < 2; nb++) {
        int c0 = nb * 16 + tig * 2;
        int c1 = nb * 16 + 8 + tig * 2;
        float2 bv0 = *(const float2*)&b1[c0];
        float2 bv1 = *(const float2*)&b1[c1];
        int rowA = m0 + warp * 16 + g;
        int rowB = rowA + 8;
        __half* hA = &d_h1h[(size_t)rowA * 32];
        __half* hB = &d_h1h[(size_t)rowB * 32];
        *(__half2*)&hA[c0] = __floats2half2_rn(eluf(acc[2 * nb][0] + bv0.x), eluf(acc[2 * nb][1] + bv0.y));
        *(__half2*)&hB[c0] = __floats2half2_rn(eluf(acc[2 * nb][2] + bv0.x), eluf(acc[2 * nb][3] + bv0.y));
        *(__half2*)&hA[c1] = __floats2half2_rn(eluf(acc[2 * nb + 1][0] + bv1.x), eluf(acc[2 * nb + 1][1] + bv1.y));
        *(__half2*)&hB[c1] = __floats2half2_rn(eluf(acc[2 * nb + 1][2] + bv1.x), eluf(acc[2 * nb + 1][3] + bv1.y));
    }
}

// ---------------- GEMM2 (tensor cores) + fused mean-pool ----------------
__global__ void __launch_bounds__(256) k_gemm2t(const float* __restrict__ b2) {
    extern __shared__ __half S[];
    __half* Asm = S;                 // [2][128][72]
    __half* Wsm = S + 2 * ABUF;      // [2][64][72]
    const int tid = threadIdx.x, lane = tid & 31, warp = tid >> 5;
    const int m0 = blockIdx.x * 128;

    const int arow = tid >> 1, ahalf = tid & 1;
    const int wrow = tid >> 2, wseg = (tid & 3) * 16;
    const __half* aSrc = &d_U2h[(size_t)(m0 + arow) * 832 + ahalf * 32];
    const __half* wSrc = &d_W2ph[wrow * 64 + wseg];

    float acc[8][4];
#pragma unroll
    for (int i = 0; i < 8; i++)
#pragma unroll
        for (int j = 0; j < 4; j++) acc[i][j] = 0.f;

    {
        int4 a0 = *(const int4*)(aSrc);
        int4 a1 = *(const int4*)(aSrc + 8);
        int4 a2 = *(const int4*)(aSrc + 16);
        int4 a3 = *(const int4*)(aSrc + 24);
        __half* ad = &Asm[arow * APITCH + ahalf * 32];
        ((int4*)ad)[0] = a0; ((int4*)ad)[1] = a1;
        ((int4*)ad)[2] = a2; ((int4*)ad)[3] = a3;
        int4 w0 = *(const int4*)(wSrc);
        int4 w1 = *(const int4*)(wSrc + 8);
        __half* wd = &Wsm[wrow * APITCH + wseg];
        ((int4*)wd)[0] = w0; ((int4*)wd)[1] = w1;
    }
    __syncthreads();

    const int aLdRow = lane & 15, aLdColGrp = (lane >> 4) * 8;
    const int bLdRow = (lane & 7) + 8 * ((lane >> 3) & 1), bLdColGrp = (lane >> 4) * 8;

    int buf = 0;
    for (int ch = 0; ch < 13; ch++) {
        int4 pa0, pa1, pa2, pa3, pw0, pw1;
        if (ch + 1 < 13) {
            const __half* as = aSrc + (ch + 1) * 64;
            pa0 = *(const int4*)(as);
            pa1 = *(const int4*)(as + 8);
            pa2 = *(const int4*)(as + 16);
            pa3 = *(const int4*)(as + 24);
            const __half* ws = wSrc + (size_t)(ch + 1) * 64 * 64;
            pw0 = *(const int4*)(ws);
            pw1 = *(const int4*)(ws + 8);
        }
        const __half* Ab = &Asm[buf * ABUF];
        const __half* Wb = &Wsm[buf * WBUF];
#pragma unroll
        for (int ks = 0; ks < 4; ks++) {
            uint32_t a[4];
            uint32_t aAddr = (uint32_t)__cvta_generic_to_shared(
                &Ab[(warp * 16 + aLdRow) * APITCH + ks * 16 + aLdColGrp]);
            ldmA4(a, aAddr);
#pragma unroll
            for (int nb = 0; nb < 4; nb++) {
                uint32_t b[4];
                uint32_t bAddr = (uint32_t)__cvta_generic_to_shared(
                    &Wb[(ks * 16 + bLdRow) * APITCH + nb * 16 + bLdColGrp]);
                ldmBT4(b, bAddr);
                mma16816(acc[2 * nb],     a, b[0], b[1]);
                mma16816(acc[2 * nb + 1], a, b[2], b[3]);
            }
        }
        if (ch + 1 < 13) {
            __half* ad = &Asm[(buf ^ 1) * ABUF + arow * APITCH + ahalf * 32];
            ((int4*)ad)[0] = pa0; ((int4*)ad)[1] = pa1;
            ((int4*)ad)[2] = pa2; ((int4*)ad)[3] = pa3;
            __half* wd = &Wsm[(buf ^ 1) * WBUF + wrow * APITCH + wseg];
            ((int4*)wd)[0] = pw0; ((int4*)wd)[1] = pw1;
        }
        __syncthreads();
        buf ^= 1;
    }

    // fused epilogue: elu + per-warp row-sum + atomic into graph accumulator
    const int tig = lane & 3;
    const int gg = (m0 + warp * 16) / 800;     // graph id (uniform per warp)
    float s[16];
#pragma unroll
    for (int nb = 0; nb < 4; nb++) {
        float2 bv0 = *(const float2*)&b2[nb * 16 + tig * 2];
        float2 bv1 = *(const float2*)&b2[nb * 16 + 8 + tig * 2];
        s[nb * 4 + 0] = eluf(acc[2 * nb][0] + bv0.x) + eluf(acc[2 * nb][2] + bv0.x);
        s[nb * 4 + 1] = eluf(acc[2 * nb][1] + bv0.y) + eluf(acc[2 * nb][3] + bv0.y);
        s[nb * 4 + 2] = eluf(acc[2 * nb + 1][0] + bv1.x) + eluf(acc[2 * nb + 1][2] + bv1.x);
        s[nb * 4 + 3] = eluf(acc[2 * nb + 1][1] + bv1.y) + eluf(acc[2 * nb + 1][3] + bv1.y);
    }
#pragma unroll
    for (int ofs = 4; ofs < 32; ofs <<= 1)
#pragma unroll
        for (int i = 0; i < 16; i++)
            s[i] += __shfl_xor_sync(0xffffffffu, s[i], ofs, 32);
    if (lane < 4) {
        float* gb = &d_gsum[gg * 64];
#pragma unroll
        for (int nb = 0; nb < 4; nb++) {
            atomicAdd(&gb[nb * 16 + lane * 2],     s[nb * 4 + 0]);
            atomicAdd(&gb[nb * 16 + lane * 2 + 1], s[nb * 4 + 1]);
            atomicAdd(&gb[nb * 16 + 8 + lane * 2],     s[nb * 4 + 2]);
            atomicAdd(&gb[nb * 16 + 8 + lane * 2 + 1], s[nb * 4 + 3]);
        }
    }
}

// ---------------- head: mean + FC + log_softmax from d_gsum ----------------
__global__ void k_head(const int* __restrict__ slices, const float* __restrict__ fcw,
                       const float* __restrict__ fcb, float* __restrict__ out) {
    int b = blockIdx.x;
    int tid = threadIdx.x;  // 32
    __shared__ float g[64];
    __shared__ float lg[30];
    float cnt = fmaxf((float)(slices[b + 1] - slices[b]), 1.f);
    for (int i = tid; i < 64; i += 32) g[i] = d_gsum[b * 64 + i] / cnt;
    __syncwarp();
    if (tid < 30) {
        float l = fcb[tid];
        for (int i = 0; i < 64; i++) l += g[i] * fcw[i * 30 + tid];
        lg[tid] = l;
    }
    __syncwarp();
    if (tid < 30) {
        float m = -1e30f;
        for (int j = 0; j < 30; j++) m = fmaxf(m, lg[j]);
        float se = 0.f;
        for (int j = 0; j < 30; j++) se += expf(lg[j] - m);
        out[b * 30 + tid] = lg[tid] - m - logf(se);
    }
}

// ---------------- launch ----------------
extern "C" void kernel_launch(void* const* d_in, const int* in_sizes, int n_in,
                              void* d_out, int out_size) {
    const float* x      = (const float*)d_in[0];
    const int*   eidx   = (const int*)d_in[1];
    const float* pseudo = (const float*)d_in[2];
    const int*   slices = (const int*)d_in[3];
    const float* W1     = (const float*)d_in[4];
    const float* root1  = (const float*)d_in[5];
    const float* b1     = (const float*)d_in[6];
    const float* W2     = (const float*)d_in[7];
    const float* root2  = (const float*)d_in[8];
    const float* b2     = (const float*)d_in[9];
    const float* fcw    = (const float*)d_in[10];
    const float* fcb    = (const float*)d_in[11];
    float* out = (float*)d_out;

    const int* src = eidx;
    const int* dst = eidx + Ee;

    const int G_SMEM = (2 * ABUF + 2 * WBUF) * 2;  // 55296 B
    cudaFuncSetAttribute(k_gemm1t, cudaFuncAttributeMaxDynamicSharedMemorySize, G_SMEM);
    cudaFuncSetAttribute(k_gemm2t, cudaFuncAttributeMaxDynamicSharedMemorySize, G_SMEM);

    k_init<<<(832 * 64 + 255) / 256, 256>>>(W1, root1, W2, root2);
    k_hist<<<(Ee + 1023) / 1024, 1024>>>(dst);
    k_scan<<<1, 1024>>>();
    k_scatter<<<(Ee + 1023) / 1024, 1024>>>(src, dst, pseudo);
    k_u1<<<Nn / 8, 256>>>(x);
    k_gemm1t<<<Nn / 128, 256, G_SMEM>>>(b1);
    k_u2<<<Nn / 4, 256>>>();
    k_gemm2t<<<Nn / 128, 256, G_SMEM>>>(b2);
    k_head<<<Bb, 32>>>(slices, fcw, fcb, out);
}